// round 5
// baseline (speedup 1.0000x reference)
#include <cuda_runtime.h>
#include <math.h>

constexpr int NL    = 4;
constexpr int DIM   = 512;
constexpr int NH    = 8;
constexpr int HD    = 64;
constexpr int DFFN  = 2048;
constexpr int SEQ   = 512;
constexpr int BATCH = 16;
constexpr int NCLS  = 3;
constexpr int MR    = BATCH * SEQ;  // 8192
constexpr int NBH   = BATCH * NH;   // 128

// ---------------- scratch ----------------
__device__ float g_x  [MR * DIM];
__device__ float g_h  [MR * DIM];
__device__ float g_q  [MR * DIM];   // [B,H,N,HD]
__device__ float g_k  [MR * DIM];   // [B,H,HD,N] (transposed)
__device__ float g_v  [MR * DIM];   // [B,H,N,HD]
__device__ float g_ctx[MR * DIM];
__device__ float g_ffn[MR * DFFN];
__device__ float g_sc [(size_t)NBH * SEQ * SEQ];  // scores [B*H,N,N]
__device__ float g_la [MR * NCLS];
__device__ float g_lb [MR * NCLS];

struct QKVArgs {
    const float* w[3];
    const float* b[3];
    float*       o[3];
};

// ---------------- embedding + PE ----------------
__global__ void embed_kernel(const int* __restrict__ src,
                             const float* __restrict__ emb) {
    int idx = blockIdx.x * blockDim.x + threadIdx.x;
    if (idx >= MR * DIM) return;
    int d = idx % DIM;
    int m = idx / DIM;
    int b = m / SEQ;
    int n = m % SEQ;
    int tok = src[n * BATCH + b];
    float e = emb[(size_t)tok * DIM + d] * 22.62741699796952f;
    int i2 = (d >> 1) * 2;
    float freq = expf((float)i2 * (-9.210340371976184f / (float)DIM));
    float ang = (float)n * freq;
    float pe = (d & 1) ? cosf(ang) : sinf(ang);
    g_x[idx] = e + pe;
}

// ---------------- LayerNorm ----------------
__global__ void ln_kernel(const float* __restrict__ in, float* __restrict__ out,
                          const float* __restrict__ gg, const float* __restrict__ bb) {
    int row = blockIdx.x;
    int t = threadIdx.x;
    const float* p = in + (size_t)row * DIM;
    float v[4];
    float s = 0.f, ss = 0.f;
#pragma unroll
    for (int i = 0; i < 4; i++) {
        float x = p[t + i * 128];
        v[i] = x; s += x; ss += x * x;
    }
#pragma unroll
    for (int off = 16; off >= 1; off >>= 1) {
        s  += __shfl_xor_sync(0xffffffffu, s, off);
        ss += __shfl_xor_sync(0xffffffffu, ss, off);
    }
    __shared__ float rs[4], rss[4];
    int w = t >> 5, lane = t & 31;
    if (lane == 0) { rs[w] = s; rss[w] = ss; }
    __syncthreads();
    float S  = rs[0] + rs[1] + rs[2] + rs[3];
    float SS = rss[0] + rss[1] + rss[2] + rss[3];
    float mean = S * (1.f / DIM);
    float var  = SS * (1.f / DIM) - mean * mean;
    float rstd = rsqrtf(var + 1e-6f);
    float* o = out + (size_t)row * DIM;
#pragma unroll
    for (int i = 0; i < 4; i++) {
        int c = t + i * 128;
        o[c] = (v[i] - mean) * rstd * gg[c] + bb[c];
    }
}

// ---------------- tf32 helpers ----------------
__device__ __forceinline__ float f2tf_f(float x) {
    unsigned r;
    asm("cvt.rna.tf32.f32 %0, %1;" : "=r"(r) : "f"(x));
    return __uint_as_float(r);
}

__device__ __forceinline__ void mma_tf32(float c[4], const unsigned a[4], const unsigned b[2]) {
    asm volatile(
        "mma.sync.aligned.m16n8k8.row.col.f32.tf32.tf32.f32 "
        "{%0,%1,%2,%3}, {%4,%5,%6,%7}, {%8,%9}, {%0,%1,%2,%3};"
        : "+f"(c[0]), "+f"(c[1]), "+f"(c[2]), "+f"(c[3])
        : "r"(a[0]), "r"(a[1]), "r"(a[2]), "r"(a[3]),
          "r"(b[0]), "r"(b[1]));
}

// ---------------- generalized tensor-core GEMM (tf32) ----------------
// C[z][M,N] = A[z][M,K] @ W[z][K,N]. BM=128, 256 threads (8 warps).
// A smem: row-major per m with k-pair permutation -> LDS.64 fragment loads.
// EPI: 0 = bias, 1 = bias + residual, 2 = bias + relu, 3 = raw
// SCAT: 0 plain, 1 QKV [B,H,N,HD], 2 K^T [B,H,HD,N], 3 ctx scatter,
//       4 fused-QKV (weights/bias/out selected by z; z==1 -> K^T scatter)
template<int BN, int WM, int EPI, int SCAT>
__global__ __launch_bounds__(256, 2)
void tgemm(const float* __restrict__ A, const float* __restrict__ W,
           const float* __restrict__ bias, const float* __restrict__ resid,
           float* __restrict__ Cout, int K, int lda, int ldb, int ldc,
           long long sA, long long sB, long long sC, QKVArgs qa) {
    constexpr int BK  = 16;
    constexpr int LDK = 18;            // A row pitch (floats)
    constexpr int LDB = BN + 8;
    constexpr int NWM = 128 / WM;
    constexpr int MT  = WM / 16;
    constexpr int BNF = BN / 16;

    __shared__ float As[2][128][LDK];  // As[m][kperm]
    __shared__ float Bs[2][BK][LDB];   // Bs[k][n]

    const int tid  = threadIdx.x;
    const int w    = tid >> 5;
    const int lane = tid & 31;
    const int g    = lane >> 2;
    const int tq   = lane & 3;
    const int wrow = (w % NWM) * WM;
    const int wcol = (w / NWM) * 32;
    const int z    = blockIdx.z;
    const int row0 = blockIdx.y * 128;
    const int col0 = blockIdx.x * BN;

    if (SCAT == 4) {
        W    = qa.w[z];
        bias = qa.b[z];
        Cout = qa.o[z];
    } else {
        A += (size_t)z * sA;
        W += (size_t)z * sB;
    }

    const int arow = tid >> 1;
    const int acol = (tid & 1) * 8;
    const int brow = tid >> 4;
    const int bcol = (tid & 15) * BNF;

    const float* Ap = A + (size_t)(row0 + arow) * lda + acol;
    const float* Wp = W + (size_t)brow * ldb + col0 + bcol;

    float C[MT][4][4];
#pragma unroll
    for (int i = 0; i < MT; i++)
#pragma unroll
        for (int j = 0; j < 4; j++)
#pragma unroll
            for (int q = 0; q < 4; q++) C[i][j][q] = 0.f;

    const int nblk = K / BK;

    float ar[8], br[BNF];
#pragma unroll
    for (int i = 0; i < 2; i++) *(float4*)(ar + i * 4) = *(const float4*)(Ap + i * 4);
#pragma unroll
    for (int i = 0; i < BNF / 4; i++) *(float4*)(br + i * 4) = *(const float4*)(Wp + i * 4);

    {
        float* as = &As[0][arow][acol];
#pragma unroll
        for (int i = 0; i < 8; i++) as[(i & 3) * 2 + (i >> 2)] = f2tf_f(ar[i]);
        float* bs = &Bs[0][brow][bcol];
#pragma unroll
        for (int i = 0; i < BNF; i++) bs[i] = f2tf_f(br[i]);
    }
    __syncthreads();

    int s = 0;
    for (int blk = 0; blk < nblk; blk++) {
        if (blk + 1 < nblk) {
            const float* ap = Ap + (blk + 1) * BK;
            const float* wp = Wp + (size_t)(blk + 1) * BK * ldb;
#pragma unroll
            for (int i = 0; i < 2; i++) *(float4*)(ar + i * 4) = *(const float4*)(ap + i * 4);
#pragma unroll
            for (int i = 0; i < BNF / 4; i++) *(float4*)(br + i * 4) = *(const float4*)(wp + i * 4);
        }

#pragma unroll
        for (int ks = 0; ks < 2; ks++) {
            const int kb = ks * 8;
            const int ca = kb + 2 * tq;
            unsigned af[MT][4], bf[4][2];
#pragma unroll
            for (int mt = 0; mt < MT; mt++) {
                int r = wrow + mt * 16 + g;
                float2 p0 = *(const float2*)&As[s][r][ca];
                float2 p1 = *(const float2*)&As[s][r + 8][ca];
                af[mt][0] = __float_as_uint(p0.x);
                af[mt][1] = __float_as_uint(p1.x);
                af[mt][2] = __float_as_uint(p0.y);
                af[mt][3] = __float_as_uint(p1.y);
            }
#pragma unroll
            for (int nt = 0; nt < 4; nt++) {
                int c = wcol + nt * 8 + g;
                bf[nt][0] = __float_as_uint(Bs[s][kb + tq][c]);
                bf[nt][1] = __float_as_uint(Bs[s][kb + tq + 4][c]);
            }
#pragma unroll
            for (int mt = 0; mt < MT; mt++)
#pragma unroll
                for (int nt = 0; nt < 4; nt++)
                    mma_tf32(C[mt][nt], af[mt], bf[nt]);
        }

        if (blk + 1 < nblk) {
            int ns = s ^ 1;
            float* as = &As[ns][arow][acol];
#pragma unroll
            for (int i = 0; i < 8; i++) as[(i & 3) * 2 + (i >> 2)] = f2tf_f(ar[i]);
            float* bs = &Bs[ns][brow][bcol];
#pragma unroll
            for (int i = 0; i < BNF; i++) bs[i] = f2tf_f(br[i]);
            __syncthreads();
            s = ns;
        }
    }

    // epilogue
#pragma unroll
    for (int mt = 0; mt < MT; mt++) {
#pragma unroll
        for (int half = 0; half < 2; half++) {
            int r = row0 + wrow + mt * 16 + g + half * 8;
#pragma unroll
            for (int nt = 0; nt < 4; nt++) {
                int c = col0 + wcol + nt * 8 + tq * 2;
                float v0 = C[mt][nt][half * 2 + 0];
                float v1 = C[mt][nt][half * 2 + 1];
                if (EPI != 3) { v0 += bias[c]; v1 += bias[c + 1]; }
                if (EPI == 1) {
                    const float* rp = resid + (size_t)r * ldc + c;
                    v0 += rp[0]; v1 += rp[1];
                }
                if (EPI == 2) { v0 = fmaxf(v0, 0.f); v1 = fmaxf(v1, 0.f); }
                if (SCAT == 1) {
                    int b = r >> 9, n = r & 511, hh = c >> 6, dd = c & 63;
                    float* op = Cout + (((size_t)(b * NH + hh)) * SEQ + n) * HD + dd;
                    *(float2*)op = make_float2(v0, v1);
                } else if (SCAT == 2) {
                    int b = r >> 9, n = r & 511, hh = c >> 6, dd = c & 63;
                    float* op = Cout + ((size_t)(b * NH + hh) * HD + dd) * SEQ + n;
                    op[0] = v0;
                    op[SEQ] = v1;
                } else if (SCAT == 3) {
                    int b = z >> 3, hh = z & 7;
                    float* op = Cout + ((size_t)(b * SEQ + r)) * DIM + hh * HD + c;
                    *(float2*)op = make_float2(v0, v1);
                } else if (SCAT == 4) {
                    int b = r >> 9, n = r & 511, hh = c >> 6, dd = c & 63;
                    if (z == 1) {
                        float* op = Cout + ((size_t)(b * NH + hh) * HD + dd) * SEQ + n;
                        op[0] = v0;
                        op[SEQ] = v1;
                    } else {
                        float* op = Cout + (((size_t)(b * NH + hh)) * SEQ + n) * HD + dd;
                        *(float2*)op = make_float2(v0, v1);
                    }
                } else {
                    *(float2*)(Cout + (size_t)z * sC + (size_t)r * ldc + c) =
                        make_float2(v0, v1);
                }
            }
        }
    }
}

// ---------------- masked softmax (in place) ----------------
__global__ void softmax_kernel(float* __restrict__ S, const int* __restrict__ lengths) {
    int row = blockIdx.x;
    int b = row >> 12;
    int t = threadIdx.x;  // 128
    float* p = S + (size_t)row * SEQ;
    int len = lengths[b];

    float v[4];
    float mx = -1e30f;
#pragma unroll
    for (int i = 0; i < 4; i++) {
        int c = t + i * 128;
        float x = p[c] * 0.125f;
        if (c >= len) x = -1e30f;
        v[i] = x;
        mx = fmaxf(mx, x);
    }
#pragma unroll
    for (int off = 16; off >= 1; off >>= 1)
        mx = fmaxf(mx, __shfl_xor_sync(0xffffffffu, mx, off));
    __shared__ float rm[4], rsum[4];
    int w = t >> 5, lane = t & 31;
    if (lane == 0) rm[w] = mx;
    __syncthreads();
    float M = fmaxf(fmaxf(rm[0], rm[1]), fmaxf(rm[2], rm[3]));

    float sum = 0.f;
#pragma unroll
    for (int i = 0; i < 4; i++) {
        float e = expf(v[i] - M);
        v[i] = e;
        sum += e;
    }
#pragma unroll
    for (int off = 16; off >= 1; off >>= 1)
        sum += __shfl_xor_sync(0xffffffffu, sum, off);
    if (lane == 0) rsum[w] = sum;
    __syncthreads();
    float inv = 1.f / (rsum[0] + rsum[1] + rsum[2] + rsum[3]);
#pragma unroll
    for (int i = 0; i < 4; i++) p[t + i * 128] = v[i] * inv;
}

// ---------------- outputs ----------------
__global__ void out1_kernel(float* __restrict__ out1) {
    int idx = blockIdx.x * blockDim.x + threadIdx.x;
    if (idx >= MR * DIM) return;
    int d = idx % DIM;
    int nb = idx / DIM;
    int b = nb % BATCH;
    int n = nb / BATCH;
    out1[idx] = g_h[((size_t)b * SEQ + n) * DIM + d];
}

__global__ void infw_kernel(const float* __restrict__ W) {
    int mrow = blockIdx.x;
    int t = threadIdx.x;  // 64
    float a[NCLS] = {0, 0, 0}, bv2[NCLS] = {0, 0, 0};
    const float* xp = g_h + (size_t)mrow * DIM;
    for (int d = t; d < DIM; d += 64) {
        float xv = xp[d];
#pragma unroll
        for (int c = 0; c < NCLS; c++) {
            a[c]   += xv * W[(size_t)d * NCLS + c];
            bv2[c] += xv * W[(size_t)(DIM + d) * NCLS + c];
        }
    }
    __shared__ float red[6][64];
#pragma unroll
    for (int c = 0; c < NCLS; c++) { red[c][t] = a[c]; red[3 + c][t] = bv2[c]; }
    __syncthreads();
    for (int sft = 32; sft >= 1; sft >>= 1) {
        if (t < sft) {
#pragma unroll
            for (int c = 0; c < 6; c++) red[c][t] += red[c][t + sft];
        }
        __syncthreads();
    }
    if (t == 0) {
#pragma unroll
        for (int c = 0; c < NCLS; c++) {
            g_la[mrow * NCLS + c] = red[c][0];
            g_lb[mrow * NCLS + c] = red[3 + c][0];
        }
    }
}

__global__ void pair_kernel(float* __restrict__ out2) {
    int idx = blockIdx.x * blockDim.x + threadIdx.x;
    if (idx >= SEQ * SEQ * BATCH) return;
    int b = idx % BATCH;
    int j = (idx / BATCH) % SEQ;
    int i = idx / (BATCH * SEQ);
    const float* lap = g_la + ((size_t)b * SEQ + i) * NCLS;
    const float* lbp = g_lb + ((size_t)b * SEQ + j) * NCLS;
    float v0 = lap[0] + lbp[0];
    float v1 = lap[1] + lbp[1];
    float v2 = lap[2] + lbp[2];
    float mx = fmaxf(v0, fmaxf(v1, v2));
    float lse = mx + logf(expf(v0 - mx) + expf(v1 - mx) + expf(v2 - mx));
    float* o = out2 + (size_t)idx * NCLS;
    o[0] = v0 - lse; o[1] = v1 - lse; o[2] = v2 - lse;
}

// ---------------- orchestration ----------------
extern "C" void kernel_launch(void* const* d_in, const int* in_sizes, int n_in,
                              void* d_out, int out_size) {
    (void)in_sizes; (void)n_in; (void)out_size;
    const int*   src     = (const int*)  d_in[0];
    const int*   lengths = (const int*)  d_in[1];
    const float* emb     = (const float*)d_in[2];
    const float* ln1_g   = (const float*)d_in[3];
    const float* ln1_b   = (const float*)d_in[4];
    const float* Wq      = (const float*)d_in[5];
    const float* bq      = (const float*)d_in[6];
    const float* Wk      = (const float*)d_in[7];
    const float* bk      = (const float*)d_in[8];
    const float* Wv      = (const float*)d_in[9];
    const float* bv      = (const float*)d_in[10];
    const float* Wo      = (const float*)d_in[11];
    const float* bo      = (const float*)d_in[12];
    const float* ln2_g   = (const float*)d_in[13];
    const float* ln2_b   = (const float*)d_in[14];
    const float* W1      = (const float*)d_in[15];
    const float* b1      = (const float*)d_in[16];
    const float* W2      = (const float*)d_in[17];
    const float* b2      = (const float*)d_in[18];
    const float* lnf_g   = (const float*)d_in[19];
    const float* lnf_b   = (const float*)d_in[20];
    const float* inf_W   = (const float*)d_in[21];
    float* out = (float*)d_out;

    float *px, *ph, *pq, *pk, *pv, *pctx, *pffn, *psc;
    cudaGetSymbolAddress((void**)&px,   g_x);
    cudaGetSymbolAddress((void**)&ph,   g_h);
    cudaGetSymbolAddress((void**)&pq,   g_q);
    cudaGetSymbolAddress((void**)&pk,   g_k);
    cudaGetSymbolAddress((void**)&pv,   g_v);
    cudaGetSymbolAddress((void**)&pctx, g_ctx);
    cudaGetSymbolAddress((void**)&pffn, g_ffn);
    cudaGetSymbolAddress((void**)&psc,  g_sc);

    embed_kernel<<<(MR * DIM + 255) / 256, 256>>>(src, emb);

    const long long sBH = (long long)SEQ * HD;
    const long long sSC = (long long)SEQ * SEQ;
    QKVArgs qe = {};

    for (int l = 0; l < NL; l++) {
        const float* wq = Wq + (size_t)l * DIM * DIM;
        const float* wk = Wk + (size_t)l * DIM * DIM;
        const float* wv = Wv + (size_t)l * DIM * DIM;
        const float* wo = Wo + (size_t)l * DIM * DIM;
        const float* w1 = W1 + (size_t)l * DIM * DFFN;
        const float* w2 = W2 + (size_t)l * DFFN * DIM;

        ln_kernel<<<MR, 128>>>(px, ph, ln1_g + l * DIM, ln1_b + l * DIM);

        // fused QKV projections: z = 0 (Q), 1 (K^T), 2 (V)
        QKVArgs qa;
        qa.w[0] = wq; qa.w[1] = wk; qa.w[2] = wv;
        qa.b[0] = bq + l * DIM; qa.b[1] = bk + l * DIM; qa.b[2] = bv + l * DIM;
        qa.o[0] = pq; qa.o[1] = pk; qa.o[2] = pv;
        dim3 gQKV(DIM / 128, MR / 128, 3);   // (4, 64, 3)
        tgemm<128, 64, 0, 4><<<gQKV, 256>>>(ph, nullptr, nullptr, nullptr, nullptr,
                                            DIM, DIM, DIM, DIM, 0, 0, 0, qa);

        // scores = Q @ K^T (batched over B*H)
        dim3 gS(SEQ / 128, SEQ / 128, NBH);  // (4, 4, 128)
        tgemm<128, 64, 3, 0><<<gS, 256>>>(pq, pk, nullptr, nullptr, psc,
                                          HD, HD, SEQ, SEQ, sBH, sBH, sSC, qe);

        softmax_kernel<<<NBH * SEQ, 128>>>(psc, lengths);

        // ctx = P @ V (batched), scatter into [B,N,D]
        dim3 gP(1, SEQ / 128, NBH);          // (1, 4, 128)
        tgemm<64, 32, 3, 3><<<gP, 256>>>(psc, pv, nullptr, nullptr, pctx,
                                         SEQ, SEQ, HD, 0, sSC, sBH, 0, qe);

        dim3 gD(DIM / 128, MR / 128, 1);     // (4, 64)
        tgemm<128, 64, 1, 0><<<gD, 256>>>(pctx, wo, bo + l * DIM, px, px,
                                          DIM, DIM, DIM, DIM, 0, 0, 0, qe);

        ln_kernel<<<MR, 128>>>(px, ph, ln2_g + l * DIM, ln2_b + l * DIM);

        dim3 gF(DFFN / 128, MR / 128, 1);    // (16, 64)
        tgemm<128, 64, 2, 0><<<gF, 256>>>(ph, w1, b1 + l * DFFN, nullptr, pffn,
                                          DIM, DIM, DFFN, DFFN, 0, 0, 0, qe);
        tgemm<128, 64, 1, 0><<<gD, 256>>>(pffn, w2, b2 + l * DIM, px, px,
                                          DFFN, DFFN, DIM, DIM, 0, 0, 0, qe);
    }

    ln_kernel<<<MR, 128>>>(px, ph, lnf_g, lnf_b);

    out1_kernel<<<(MR * DIM + 255) / 256, 256>>>(out);
    infw_kernel<<<MR, 64>>>(inf_W);
    pair_kernel<<<(SEQ * SEQ * BATCH + 255) / 256, 256>>>(out + (size_t)MR * DIM);
}

// round 6
// speedup vs baseline: 1.6931x; 1.6931x over previous
#include <cuda_runtime.h>
#include <math.h>

constexpr int NL    = 4;
constexpr int DIM   = 512;
constexpr int NH    = 8;
constexpr int HD    = 64;
constexpr int DFFN  = 2048;
constexpr int SEQ   = 512;
constexpr int BATCH = 16;
constexpr int NCLS  = 3;
constexpr int MR    = BATCH * SEQ;  // 8192
constexpr int NBH   = BATCH * NH;   // 128

// ---------------- scratch ----------------
__device__ float g_x  [MR * DIM];
__device__ float g_h  [MR * DIM];
__device__ float g_q  [MR * DIM];   // [B,H,N,HD]
__device__ float g_k  [MR * DIM];   // [B,H,HD,N] (transposed)
__device__ float g_v  [MR * DIM];   // [B,H,N,HD]
__device__ float g_ctx[MR * DIM];
__device__ float g_ffn[MR * DFFN];
__device__ float g_sc [(size_t)NBH * SEQ * SEQ];  // exp(scores) [B*H,N,N]
__device__ float g_rs [NBH * SEQ];                // per-row exp sums
__device__ float g_la [MR * NCLS];
__device__ float g_lb [MR * NCLS];

struct QKVArgs {
    const float* w[3];
    const float* b[3];
    float*       o[3];
};

// ---------------- embedding + PE ----------------
__global__ void embed_kernel(const int* __restrict__ src,
                             const float* __restrict__ emb) {
    int idx = blockIdx.x * blockDim.x + threadIdx.x;
    if (idx >= MR * DIM) return;
    int d = idx % DIM;
    int m = idx / DIM;
    int b = m / SEQ;
    int n = m % SEQ;
    int tok = src[n * BATCH + b];
    float e = emb[(size_t)tok * DIM + d] * 22.62741699796952f;
    int i2 = (d >> 1) * 2;
    float freq = expf((float)i2 * (-9.210340371976184f / (float)DIM));
    float ang = (float)n * freq;
    float pe = (d & 1) ? cosf(ang) : sinf(ang);
    g_x[idx] = e + pe;
}

// ---------------- LayerNorm ----------------
__global__ void ln_kernel(const float* __restrict__ in, float* __restrict__ out,
                          const float* __restrict__ gg, const float* __restrict__ bb) {
    int row = blockIdx.x;
    int t = threadIdx.x;
    const float* p = in + (size_t)row * DIM;
    float v[4];
    float s = 0.f, ss = 0.f;
#pragma unroll
    for (int i = 0; i < 4; i++) {
        float x = p[t + i * 128];
        v[i] = x; s += x; ss += x * x;
    }
#pragma unroll
    for (int off = 16; off >= 1; off >>= 1) {
        s  += __shfl_xor_sync(0xffffffffu, s, off);
        ss += __shfl_xor_sync(0xffffffffu, ss, off);
    }
    __shared__ float rs[4], rss[4];
    int w = t >> 5, lane = t & 31;
    if (lane == 0) { rs[w] = s; rss[w] = ss; }
    __syncthreads();
    float S  = rs[0] + rs[1] + rs[2] + rs[3];
    float SS = rss[0] + rss[1] + rss[2] + rss[3];
    float mean = S * (1.f / DIM);
    float var  = SS * (1.f / DIM) - mean * mean;
    float rstd = rsqrtf(var + 1e-6f);
    float* o = out + (size_t)row * DIM;
#pragma unroll
    for (int i = 0; i < 4; i++) {
        int c = t + i * 128;
        o[c] = (v[i] - mean) * rstd * gg[c] + bb[c];
    }
}

// ---------------- rowsum zero ----------------
__global__ void zero_rs_kernel() {
    int idx = blockIdx.x * blockDim.x + threadIdx.x;
    if (idx < NBH * SEQ) g_rs[idx] = 0.f;
}

// ---------------- tf32 helpers ----------------
__device__ __forceinline__ float f2tf_f(float x) {
    unsigned r;
    asm("cvt.rna.tf32.f32 %0, %1;" : "=r"(r) : "f"(x));
    return __uint_as_float(r);
}

__device__ __forceinline__ void mma_tf32(float c[4], const unsigned a[4], const unsigned b[2]) {
    asm volatile(
        "mma.sync.aligned.m16n8k8.row.col.f32.tf32.tf32.f32 "
        "{%0,%1,%2,%3}, {%4,%5,%6,%7}, {%8,%9}, {%0,%1,%2,%3};"
        : "+f"(c[0]), "+f"(c[1]), "+f"(c[2]), "+f"(c[3])
        : "r"(a[0]), "r"(a[1]), "r"(a[2]), "r"(a[3]),
          "r"(b[0]), "r"(b[1]));
}

// ---------------- generalized tensor-core GEMM (tf32) ----------------
// C[z][M,N] = A[z][M,K] @ W[z][K,N]. BM=128, 256 threads (8 warps).
// A smem: [k][m] layout, stride 136 — conflict-free LDS.32 fragment loads.
// EPI: 0 bias, 1 bias+residual, 2 bias+relu, 3 raw,
//      4 divide-by-rowsum (PV), 5 scale+mask+exp+rowsum-atomic (scores)
// SCAT: 0 plain, 3 ctx scatter, 4 fused-QKV (z selects W/bias/out; z==1 -> K^T)
template<int BN, int WM, int EPI, int SCAT>
__global__ __launch_bounds__(256, 2)
void tgemm(const float* __restrict__ A, const float* __restrict__ W,
           const float* __restrict__ bias, const float* __restrict__ resid,
           float* __restrict__ Cout, int K, int lda, int ldb, int ldc,
           long long sA, long long sB, long long sC,
           const int* __restrict__ lens, float* __restrict__ rowsum, QKVArgs qa) {
    constexpr int BK  = 16;
    constexpr int LDA = 136;
    constexpr int LDB = BN + 8;
    constexpr int NWM = 128 / WM;
    constexpr int MT  = WM / 16;
    constexpr int BNF = BN / 16;

    __shared__ float As[2][BK][LDA];
    __shared__ float Bs[2][BK][LDB];

    const int tid  = threadIdx.x;
    const int w    = tid >> 5;
    const int lane = tid & 31;
    const int g    = lane >> 2;
    const int tq   = lane & 3;
    const int wrow = (w % NWM) * WM;
    const int wcol = (w / NWM) * 32;
    const int z    = blockIdx.z;
    const int row0 = blockIdx.y * 128;
    const int col0 = blockIdx.x * BN;

    if (SCAT == 4) {
        W    = qa.w[z];
        bias = qa.b[z];
        Cout = qa.o[z];
    } else {
        A += (size_t)z * sA;
        W += (size_t)z * sB;
    }

    const int arow = tid >> 1;
    const int acol = (tid & 1) * 8;
    const int brow = tid >> 4;
    const int bcol = (tid & 15) * BNF;

    const float* Ap = A + (size_t)(row0 + arow) * lda + acol;
    const float* Wp = W + (size_t)brow * ldb + col0 + bcol;

    float C[MT][4][4];
#pragma unroll
    for (int i = 0; i < MT; i++)
#pragma unroll
        for (int j = 0; j < 4; j++)
#pragma unroll
            for (int q = 0; q < 4; q++) C[i][j][q] = 0.f;

    const int nblk = K / BK;

    float ar[8], br[BNF];
#pragma unroll
    for (int i = 0; i < 2; i++) *(float4*)(ar + i * 4) = *(const float4*)(Ap + i * 4);
#pragma unroll
    for (int i = 0; i < BNF / 4; i++) *(float4*)(br + i * 4) = *(const float4*)(Wp + i * 4);

    {
        float* as = &As[0][acol][arow];
#pragma unroll
        for (int i = 0; i < 8; i++) as[i * LDA] = f2tf_f(ar[i]);
        float* bs = &Bs[0][brow][bcol];
#pragma unroll
        for (int i = 0; i < BNF; i++) bs[i] = f2tf_f(br[i]);
    }
    __syncthreads();

    int s = 0;
    for (int blk = 0; blk < nblk; blk++) {
        if (blk + 1 < nblk) {
            const float* ap = Ap + (blk + 1) * BK;
            const float* wp = Wp + (size_t)(blk + 1) * BK * ldb;
#pragma unroll
            for (int i = 0; i < 2; i++) *(float4*)(ar + i * 4) = *(const float4*)(ap + i * 4);
#pragma unroll
            for (int i = 0; i < BNF / 4; i++) *(float4*)(br + i * 4) = *(const float4*)(wp + i * 4);
        }

#pragma unroll
        for (int ks = 0; ks < 2; ks++) {
            const int kb = ks * 8;
            unsigned af[MT][4], bf[4][2];
#pragma unroll
            for (int mt = 0; mt < MT; mt++) {
                int r = wrow + mt * 16 + g;
                af[mt][0] = __float_as_uint(As[s][kb + tq][r]);
                af[mt][1] = __float_as_uint(As[s][kb + tq][r + 8]);
                af[mt][2] = __float_as_uint(As[s][kb + tq + 4][r]);
                af[mt][3] = __float_as_uint(As[s][kb + tq + 4][r + 8]);
            }
#pragma unroll
            for (int nt = 0; nt < 4; nt++) {
                int c = wcol + nt * 8 + g;
                bf[nt][0] = __float_as_uint(Bs[s][kb + tq][c]);
                bf[nt][1] = __float_as_uint(Bs[s][kb + tq + 4][c]);
            }
#pragma unroll
            for (int mt = 0; mt < MT; mt++)
#pragma unroll
                for (int nt = 0; nt < 4; nt++)
                    mma_tf32(C[mt][nt], af[mt], bf[nt]);
        }

        if (blk + 1 < nblk) {
            int ns = s ^ 1;
            float* as = &As[ns][acol][arow];
#pragma unroll
            for (int i = 0; i < 8; i++) as[i * LDA] = f2tf_f(ar[i]);
            float* bs = &Bs[ns][brow][bcol];
#pragma unroll
            for (int i = 0; i < BNF; i++) bs[i] = f2tf_f(br[i]);
            __syncthreads();
            s = ns;
        }
    }

    // epilogue
    int len = 0;
    if (EPI == 5) len = lens[z >> 3];

#pragma unroll
    for (int mt = 0; mt < MT; mt++) {
#pragma unroll
        for (int half = 0; half < 2; half++) {
            int r = row0 + wrow + mt * 16 + g + half * 8;
            float inv = 1.f;
            if (EPI == 4) inv = 1.f / rowsum[z * SEQ + r];
            float rsum = 0.f;
#pragma unroll
            for (int nt = 0; nt < 4; nt++) {
                int c = col0 + wcol + nt * 8 + tq * 2;
                float v0 = C[mt][nt][half * 2 + 0];
                float v1 = C[mt][nt][half * 2 + 1];
                if (EPI == 0 || EPI == 1 || EPI == 2) { v0 += bias[c]; v1 += bias[c + 1]; }
                if (EPI == 1) {
                    const float* rp = resid + (size_t)r * ldc + c;
                    v0 += rp[0]; v1 += rp[1];
                }
                if (EPI == 2) { v0 = fmaxf(v0, 0.f); v1 = fmaxf(v1, 0.f); }
                if (EPI == 4) { v0 *= inv; v1 *= inv; }
                if (EPI == 5) {
                    v0 = (c     < len) ? expf(v0 * 0.125f) : 0.f;
                    v1 = (c + 1 < len) ? expf(v1 * 0.125f) : 0.f;
                    rsum += v0 + v1;
                }
                if (SCAT == 3) {
                    int b = z >> 3, hh = z & 7;
                    float* op = Cout + ((size_t)(b * SEQ + r)) * DIM + hh * HD + c;
                    *(float2*)op = make_float2(v0, v1);
                } else if (SCAT == 4) {
                    int b = r >> 9, n = r & 511, hh = c >> 6, dd = c & 63;
                    if (z == 1) {
                        float* op = Cout + ((size_t)(b * NH + hh) * HD + dd) * SEQ + n;
                        op[0] = v0;
                        op[SEQ] = v1;
                    } else {
                        float* op = Cout + (((size_t)(b * NH + hh)) * SEQ + n) * HD + dd;
                        *(float2*)op = make_float2(v0, v1);
                    }
                } else {
                    *(float2*)(Cout + (size_t)z * sC + (size_t)r * ldc + c) =
                        make_float2(v0, v1);
                }
            }
            if (EPI == 5) {
                rsum += __shfl_xor_sync(0xffffffffu, rsum, 1);
                rsum += __shfl_xor_sync(0xffffffffu, rsum, 2);
                if (tq == 0) atomicAdd(&rowsum[z * SEQ + r], rsum);
            }
        }
    }
}

// ---------------- outputs ----------------
__global__ void out1_kernel(float* __restrict__ out1) {
    int idx = blockIdx.x * blockDim.x + threadIdx.x;
    if (idx >= MR * DIM) return;
    int d = idx % DIM;
    int nb = idx / DIM;
    int b = nb % BATCH;
    int n = nb / BATCH;
    out1[idx] = g_h[((size_t)b * SEQ + n) * DIM + d];
}

__global__ void infw_kernel(const float* __restrict__ W) {
    int mrow = blockIdx.x;
    int t = threadIdx.x;  // 64
    float a[NCLS] = {0, 0, 0}, bv2[NCLS] = {0, 0, 0};
    const float* xp = g_h + (size_t)mrow * DIM;
    for (int d = t; d < DIM; d += 64) {
        float xv = xp[d];
#pragma unroll
        for (int c = 0; c < NCLS; c++) {
            a[c]   += xv * W[(size_t)d * NCLS + c];
            bv2[c] += xv * W[(size_t)(DIM + d) * NCLS + c];
        }
    }
    __shared__ float red[6][64];
#pragma unroll
    for (int c = 0; c < NCLS; c++) { red[c][t] = a[c]; red[3 + c][t] = bv2[c]; }
    __syncthreads();
    for (int sft = 32; sft >= 1; sft >>= 1) {
        if (t < sft) {
#pragma unroll
            for (int c = 0; c < 6; c++) red[c][t] += red[c][t + sft];
        }
        __syncthreads();
    }
    if (t == 0) {
#pragma unroll
        for (int c = 0; c < NCLS; c++) {
            g_la[mrow * NCLS + c] = red[c][0];
            g_lb[mrow * NCLS + c] = red[3 + c][0];
        }
    }
}

__global__ void pair_kernel(float* __restrict__ out2) {
    int idx = blockIdx.x * blockDim.x + threadIdx.x;
    if (idx >= SEQ * SEQ * BATCH) return;
    int b = idx % BATCH;
    int j = (idx / BATCH) % SEQ;
    int i = idx / (BATCH * SEQ);
    const float* lap = g_la + ((size_t)b * SEQ + i) * NCLS;
    const float* lbp = g_lb + ((size_t)b * SEQ + j) * NCLS;
    float v0 = lap[0] + lbp[0];
    float v1 = lap[1] + lbp[1];
    float v2 = lap[2] + lbp[2];
    float mx = fmaxf(v0, fmaxf(v1, v2));
    float lse = mx + logf(expf(v0 - mx) + expf(v1 - mx) + expf(v2 - mx));
    float* o = out2 + (size_t)idx * NCLS;
    o[0] = v0 - lse; o[1] = v1 - lse; o[2] = v2 - lse;
}

// ---------------- orchestration ----------------
extern "C" void kernel_launch(void* const* d_in, const int* in_sizes, int n_in,
                              void* d_out, int out_size) {
    (void)in_sizes; (void)n_in; (void)out_size;
    const int*   src     = (const int*)  d_in[0];
    const int*   lengths = (const int*)  d_in[1];
    const float* emb     = (const float*)d_in[2];
    const float* ln1_g   = (const float*)d_in[3];
    const float* ln1_b   = (const float*)d_in[4];
    const float* Wq      = (const float*)d_in[5];
    const float* bq      = (const float*)d_in[6];
    const float* Wk      = (const float*)d_in[7];
    const float* bk      = (const float*)d_in[8];
    const float* Wv      = (const float*)d_in[9];
    const float* bv      = (const float*)d_in[10];
    const float* Wo      = (const float*)d_in[11];
    const float* bo      = (const float*)d_in[12];
    const float* ln2_g   = (const float*)d_in[13];
    const float* ln2_b   = (const float*)d_in[14];
    const float* W1      = (const float*)d_in[15];
    const float* b1      = (const float*)d_in[16];
    const float* W2      = (const float*)d_in[17];
    const float* b2      = (const float*)d_in[18];
    const float* lnf_g   = (const float*)d_in[19];
    const float* lnf_b   = (const float*)d_in[20];
    const float* inf_W   = (const float*)d_in[21];
    float* out = (float*)d_out;

    float *px, *ph, *pq, *pk, *pv, *pctx, *pffn, *psc, *prs;
    cudaGetSymbolAddress((void**)&px,   g_x);
    cudaGetSymbolAddress((void**)&ph,   g_h);
    cudaGetSymbolAddress((void**)&pq,   g_q);
    cudaGetSymbolAddress((void**)&pk,   g_k);
    cudaGetSymbolAddress((void**)&pv,   g_v);
    cudaGetSymbolAddress((void**)&pctx, g_ctx);
    cudaGetSymbolAddress((void**)&pffn, g_ffn);
    cudaGetSymbolAddress((void**)&psc,  g_sc);
    cudaGetSymbolAddress((void**)&prs,  g_rs);

    embed_kernel<<<(MR * DIM + 255) / 256, 256>>>(src, emb);

    const long long sBH = (long long)SEQ * HD;
    const long long sSC = (long long)SEQ * SEQ;
    QKVArgs qe = {};

    for (int l = 0; l < NL; l++) {
        const float* wq = Wq + (size_t)l * DIM * DIM;
        const float* wk = Wk + (size_t)l * DIM * DIM;
        const float* wv = Wv + (size_t)l * DIM * DIM;
        const float* wo = Wo + (size_t)l * DIM * DIM;
        const float* w1 = W1 + (size_t)l * DIM * DFFN;
        const float* w2 = W2 + (size_t)l * DFFN * DIM;

        ln_kernel<<<MR, 128>>>(px, ph, ln1_g + l * DIM, ln1_b + l * DIM);

        // fused QKV projections: z = 0 (Q), 1 (K^T), 2 (V)
        QKVArgs qa;
        qa.w[0] = wq; qa.w[1] = wk; qa.w[2] = wv;
        qa.b[0] = bq + l * DIM; qa.b[1] = bk + l * DIM; qa.b[2] = bv + l * DIM;
        qa.o[0] = pq; qa.o[1] = pk; qa.o[2] = pv;
        dim3 gQKV(DIM / 128, MR / 128, 3);
        tgemm<128, 64, 0, 4><<<gQKV, 256>>>(ph, nullptr, nullptr, nullptr, nullptr,
                                            DIM, DIM, DIM, DIM, 0, 0, 0,
                                            nullptr, nullptr, qa);

        zero_rs_kernel<<<(NBH * SEQ + 255) / 256, 256>>>();

        // P_unnorm = exp(mask(QK^T/8)) (batched over B*H), rowsums accumulated
        dim3 gS(SEQ / 128, SEQ / 128, NBH);
        tgemm<128, 64, 5, 0><<<gS, 256>>>(pq, pk, nullptr, nullptr, psc,
                                          HD, HD, SEQ, SEQ, sBH, sBH, sSC,
                                          lengths, prs, qe);

        // ctx = (P_unnorm @ V) / rowsum, scatter into [B,N,D]
        dim3 gP(1, SEQ / 128, NBH);
        tgemm<64, 32, 4, 3><<<gP, 256>>>(psc, pv, nullptr, nullptr, pctx,
                                         SEQ, SEQ, HD, 0, sSC, sBH, 0,
                                         nullptr, prs, qe);

        dim3 gD(DIM / 128, MR / 128, 1);
        tgemm<128, 64, 1, 0><<<gD, 256>>>(pctx, wo, bo + l * DIM, px, px,
                                          DIM, DIM, DIM, DIM, 0, 0, 0,
                                          nullptr, nullptr, qe);

        ln_kernel<<<MR, 128>>>(px, ph, ln2_g + l * DIM, ln2_b + l * DIM);

        dim3 gF(DFFN / 128, MR / 128, 1);
        tgemm<128, 64, 2, 0><<<gF, 256>>>(ph, w1, b1 + l * DFFN, nullptr, pffn,
                                          DIM, DIM, DFFN, DFFN, 0, 0, 0,
                                          nullptr, nullptr, qe);
        tgemm<128, 64, 1, 0><<<gD, 256>>>(pffn, w2, b2 + l * DIM, px, px,
                                          DFFN, DFFN, DIM, DIM, 0, 0, 0,
                                          nullptr, nullptr, qe);
    }

    ln_kernel<<<MR, 128>>>(px, ph, lnf_g, lnf_b);

    out1_kernel<<<(MR * DIM + 255) / 256, 256>>>(out);
    infw_kernel<<<MR, 64>>>(inf_W);
    pair_kernel<<<(SEQ * SEQ * BATCH + 255) / 256, 256>>>(out + (size_t)MR * DIM);
}

// round 8
// speedup vs baseline: 2.5423x; 1.5016x over previous
#include <cuda_runtime.h>
#include <cuda_fp16.h>
#include <math.h>

constexpr int NL    = 4;
constexpr int DIM   = 512;
constexpr int NH    = 8;
constexpr int HD    = 64;
constexpr int DFFN  = 2048;
constexpr int SEQ   = 512;
constexpr int BATCH = 16;
constexpr int NCLS  = 3;
constexpr int MR    = BATCH * SEQ;  // 8192
constexpr int NBH   = BATCH * NH;   // 128

// ---------------- scratch ----------------
__device__ float  g_x  [MR * DIM];
__device__ float  g_h  [MR * DIM];
__device__ float  g_q  [MR * DIM];   // [B,H,N,HD]
__device__ float  g_k  [MR * DIM];   // [B,H,HD,N] (transposed)
__device__ float  g_v  [MR * DIM];   // [B,H,N,HD]
__device__ float  g_ctx[MR * DIM];
__device__ float  g_ffn[MR * DFFN];
__device__ __half g_sc [(size_t)NBH * SEQ * SEQ];  // exp(scores), fp16
__device__ float  g_rs [NBH * SEQ];                // per-row exp sums
__device__ float  g_la [MR * NCLS];
__device__ float  g_lb [MR * NCLS];

struct QKVArgs {
    const float* w[3];
    const float* b[3];
    float*       o[3];
};

// ---------------- embedding + PE ----------------
__global__ void embed_kernel(const int* __restrict__ src,
                             const float* __restrict__ emb) {
    int idx = blockIdx.x * blockDim.x + threadIdx.x;
    if (idx >= MR * DIM) return;
    int d = idx % DIM;
    int m = idx / DIM;
    int b = m / SEQ;
    int n = m % SEQ;
    int tok = src[n * BATCH + b];
    float e = emb[(size_t)tok * DIM + d] * 22.62741699796952f;
    int i2 = (d >> 1) * 2;
    float freq = expf((float)i2 * (-9.210340371976184f / (float)DIM));
    float ang = (float)n * freq;
    float pe = (d & 1) ? cosf(ang) : sinf(ang);
    g_x[idx] = e + pe;
}

// ---------------- LayerNorm ----------------
__global__ void ln_kernel(const float* __restrict__ in, float* __restrict__ out,
                          const float* __restrict__ gg, const float* __restrict__ bb) {
    int row = blockIdx.x;
    int t = threadIdx.x;
    const float* p = in + (size_t)row * DIM;
    float v[4];
    float s = 0.f, ss = 0.f;
#pragma unroll
    for (int i = 0; i < 4; i++) {
        float x = p[t + i * 128];
        v[i] = x; s += x; ss += x * x;
    }
#pragma unroll
    for (int off = 16; off >= 1; off >>= 1) {
        s  += __shfl_xor_sync(0xffffffffu, s, off);
        ss += __shfl_xor_sync(0xffffffffu, ss, off);
    }
    __shared__ float rs[4], rss[4];
    int w = t >> 5, lane = t & 31;
    if (lane == 0) { rs[w] = s; rss[w] = ss; }
    __syncthreads();
    float S  = rs[0] + rs[1] + rs[2] + rs[3];
    float SS = rss[0] + rss[1] + rss[2] + rss[3];
    float mean = S * (1.f / DIM);
    float var  = SS * (1.f / DIM) - mean * mean;
    float rstd = rsqrtf(var + 1e-6f);
    float* o = out + (size_t)row * DIM;
#pragma unroll
    for (int i = 0; i < 4; i++) {
        int c = t + i * 128;
        o[c] = (v[i] - mean) * rstd * gg[c] + bb[c];
    }
}

// ---------------- rowsum zero ----------------
__global__ void zero_rs_kernel() {
    int idx = blockIdx.x * blockDim.x + threadIdx.x;
    if (idx < NBH * SEQ) g_rs[idx] = 0.f;
}

// ---------------- fp16 mma helpers ----------------
__device__ __forceinline__ unsigned pack_h2(float a, float b) {
    __half2 h = __floats2half2_rn(a, b);
    return *(unsigned*)&h;
}

__device__ __forceinline__ unsigned s2u(const void* p) {
    return (unsigned)__cvta_generic_to_shared(p);
}

__device__ __forceinline__ void mma_f16(float c[4], const unsigned a[4], const unsigned b[2]) {
    asm volatile(
        "mma.sync.aligned.m16n8k16.row.col.f32.f16.f16.f32 "
        "{%0,%1,%2,%3}, {%4,%5,%6,%7}, {%8,%9}, {%0,%1,%2,%3};"
        : "+f"(c[0]), "+f"(c[1]), "+f"(c[2]), "+f"(c[3])
        : "r"(a[0]), "r"(a[1]), "r"(a[2]), "r"(a[3]),
          "r"(b[0]), "r"(b[1]));
}

// ---------------- fp16 tensor-core GEMM ----------------
// C[z][M,N] = A[z][M,K] @ W[z][K,N]. BM=128, BK=32, 256 threads (8 warps).
// A smem [m][k] pitch 40 halves (ldmatrix.x4), B smem [k][n] pitch BN+8
// (ldmatrix.x2.trans). Both conflict-free.
// EPI: 0 bias, 1 bias+residual, 2 bias+relu, 4 /rowsum (PV),
//      5 scale+mask+exp (rounded to fp16) + rowsum atomics (scores)
// SCAT: 0 plain, 3 ctx scatter, 4 fused-QKV (z selects; z==1 -> K^T scatter)
// AH: A operand is __half in gmem.  CH: C stored as __half.
template<int BN, int WM, int EPI, int SCAT, int AH, int CH>
__global__ __launch_bounds__(256, 2)
void tgemm(const void* __restrict__ Av, const float* __restrict__ W,
           const float* __restrict__ bias, const float* __restrict__ resid,
           void* __restrict__ Cv, int K, int lda, int ldb, int ldc,
           long long sA, long long sB, long long sC,
           const int* __restrict__ lens, float* __restrict__ rowsum, QKVArgs qa) {
    constexpr int BK  = 32;
    constexpr int LDA = 40;        // halves per A row
    constexpr int LDB = BN + 8;    // halves per B row
    constexpr int NWM = 128 / WM;
    constexpr int MT  = WM / 16;
    constexpr int BROWS = (BN == 128) ? 2 : 1;  // B rows per thread per stage

    __shared__ __half As[2][128][LDA];
    __shared__ __half Bs[2][BK][LDB];

    const int tid  = threadIdx.x;
    const int w    = tid >> 5;
    const int lane = tid & 31;
    const int g    = lane >> 2;
    const int tq   = lane & 3;
    const int lane15 = lane & 15;
    const int aoff = (lane >> 4) << 3;      // 0 or 8 (k offset for ldmatrix x4)
    const int wrow = (w % NWM) * WM;
    const int wcol = (w / NWM) * 32;
    const int z    = blockIdx.z;
    const int row0 = blockIdx.y * 128;
    const int col0 = blockIdx.x * BN;

    const float* bias_p = bias;
    float* Cf = (float*)Cv;
    __half* Ch = (__half*)Cv;
    if (SCAT == 4) {
        W      = qa.w[z];
        bias_p = qa.b[z];
        Cf     = qa.o[z];
    } else {
        W += (size_t)z * sB;
    }

    // loaders
    const int arow = tid >> 1;                 // 0..127
    const int acol = (tid & 1) * 16;           // 0 or 16 (k offset)
    const int brow = (BN == 128) ? (tid >> 4) : (tid >> 3);
    const int bcol = (BN == 128) ? (tid & 15) * 8 : (tid & 7) * 8;

    const float*  Apf = (const float*) Av + (AH ? 0 : ((size_t)z * sA + (size_t)(row0 + arow) * lda + acol));
    const __half* Aph = (const __half*)Av + (AH ? ((size_t)z * sA + (size_t)(row0 + arow) * lda + acol) : 0);
    const float*  Wp  = W + (size_t)brow * ldb + col0 + bcol;

    float C[MT][4][4];
#pragma unroll
    for (int i = 0; i < MT; i++)
#pragma unroll
        for (int j = 0; j < 4; j++)
#pragma unroll
            for (int q = 0; q < 4; q++) C[i][j][q] = 0.f;

    const int nblk = K / BK;

    unsigned ah[8];
    uint4    ahv, ahv2;
    unsigned bh[BROWS * 4];

    // prefetch block 0
    if (AH) {
        ahv  = *(const uint4*)(Aph);
        ahv2 = *(const uint4*)(Aph + 8);
    } else {
#pragma unroll
        for (int i = 0; i < 4; i++) {
            float4 f = *(const float4*)(Apf + i * 4);
            ah[2 * i]     = pack_h2(f.x, f.y);
            ah[2 * i + 1] = pack_h2(f.z, f.w);
        }
    }
#pragma unroll
    for (int rr = 0; rr < BROWS; rr++) {
        const float* wp = Wp + (size_t)rr * 16 * ldb;
        float4 f0 = *(const float4*)(wp);
        float4 f1 = *(const float4*)(wp + 4);
        bh[rr * 4 + 0] = pack_h2(f0.x, f0.y);
        bh[rr * 4 + 1] = pack_h2(f0.z, f0.w);
        bh[rr * 4 + 2] = pack_h2(f1.x, f1.y);
        bh[rr * 4 + 3] = pack_h2(f1.z, f1.w);
    }

    // store block 0
    if (AH) {
        *(uint4*)&As[0][arow][acol]     = ahv;
        *(uint4*)&As[0][arow][acol + 8] = ahv2;
    } else {
        *(uint4*)&As[0][arow][acol]     = make_uint4(ah[0], ah[1], ah[2], ah[3]);
        *(uint4*)&As[0][arow][acol + 8] = make_uint4(ah[4], ah[5], ah[6], ah[7]);
    }
#pragma unroll
    for (int rr = 0; rr < BROWS; rr++)
        *(uint4*)&Bs[0][brow + rr * 16][bcol] =
            make_uint4(bh[rr * 4 + 0], bh[rr * 4 + 1], bh[rr * 4 + 2], bh[rr * 4 + 3]);
    __syncthreads();

    int s = 0;
    for (int blk = 0; blk < nblk; blk++) {
        if (blk + 1 < nblk) {
            const int k0 = (blk + 1) * BK;
            if (AH) {
                ahv  = *(const uint4*)(Aph + k0);
                ahv2 = *(const uint4*)(Aph + k0 + 8);
            } else {
#pragma unroll
                for (int i = 0; i < 4; i++) {
                    float4 f = *(const float4*)(Apf + k0 + i * 4);
                    ah[2 * i]     = pack_h2(f.x, f.y);
                    ah[2 * i + 1] = pack_h2(f.z, f.w);
                }
            }
#pragma unroll
            for (int rr = 0; rr < BROWS; rr++) {
                const float* wp = Wp + (size_t)(k0 + rr * 16) * ldb;
                float4 f0 = *(const float4*)(wp);
                float4 f1 = *(const float4*)(wp + 4);
                bh[rr * 4 + 0] = pack_h2(f0.x, f0.y);
                bh[rr * 4 + 1] = pack_h2(f0.z, f0.w);
                bh[rr * 4 + 2] = pack_h2(f1.x, f1.y);
                bh[rr * 4 + 3] = pack_h2(f1.z, f1.w);
            }
        }

#pragma unroll
        for (int ks = 0; ks < 2; ks++) {
            const int kb = ks * 16;
            unsigned af[MT][4], bf[4][2];
#pragma unroll
            for (int mt = 0; mt < MT; mt++) {
                unsigned addr = s2u(&As[s][wrow + mt * 16 + lane15][kb + aoff]);
                asm volatile("ldmatrix.sync.aligned.m8n8.x4.shared.b16 {%0,%1,%2,%3}, [%4];"
                             : "=r"(af[mt][0]), "=r"(af[mt][1]), "=r"(af[mt][2]), "=r"(af[mt][3])
                             : "r"(addr));
            }
#pragma unroll
            for (int nt = 0; nt < 4; nt++) {
                unsigned addr = s2u(&Bs[s][kb + lane15][wcol + nt * 8]);
                asm volatile("ldmatrix.sync.aligned.m8n8.x2.trans.shared.b16 {%0,%1}, [%2];"
                             : "=r"(bf[nt][0]), "=r"(bf[nt][1])
                             : "r"(addr));
            }
#pragma unroll
            for (int mt = 0; mt < MT; mt++)
#pragma unroll
                for (int nt = 0; nt < 4; nt++)
                    mma_f16(C[mt][nt], af[mt], bf[nt]);
        }

        if (blk + 1 < nblk) {
            int ns = s ^ 1;
            if (AH) {
                *(uint4*)&As[ns][arow][acol]     = ahv;
                *(uint4*)&As[ns][arow][acol + 8] = ahv2;
            } else {
                *(uint4*)&As[ns][arow][acol]     = make_uint4(ah[0], ah[1], ah[2], ah[3]);
                *(uint4*)&As[ns][arow][acol + 8] = make_uint4(ah[4], ah[5], ah[6], ah[7]);
            }
#pragma unroll
            for (int rr = 0; rr < BROWS; rr++)
                *(uint4*)&Bs[ns][brow + rr * 16][bcol] =
                    make_uint4(bh[rr * 4 + 0], bh[rr * 4 + 1], bh[rr * 4 + 2], bh[rr * 4 + 3]);
            __syncthreads();
            s = ns;
        }
    }

    // epilogue
    int len = 0;
    if (EPI == 5) len = lens[z >> 3];

#pragma unroll
    for (int mt = 0; mt < MT; mt++) {
#pragma unroll
        for (int half = 0; half < 2; half++) {
            int r = row0 + wrow + mt * 16 + g + half * 8;
            float inv = 1.f;
            if (EPI == 4) inv = 1.f / rowsum[z * SEQ + r];
            float rsum = 0.f;
#pragma unroll
            for (int nt = 0; nt < 4; nt++) {
                int c = col0 + wcol + nt * 8 + tq * 2;
                float v0 = C[mt][nt][half * 2 + 0];
                float v1 = C[mt][nt][half * 2 + 1];
                if (EPI == 0 || EPI == 1 || EPI == 2) { v0 += bias_p[c]; v1 += bias_p[c + 1]; }
                if (EPI == 1) {
                    const float* rp = resid + (size_t)r * ldc + c;
                    v0 += rp[0]; v1 += rp[1];
                }
                if (EPI == 2) { v0 = fmaxf(v0, 0.f); v1 = fmaxf(v1, 0.f); }
                if (EPI == 4) { v0 *= inv; v1 *= inv; }
                if (EPI == 5) {
                    v0 = (c     < len) ? expf(v0 * 0.125f) : 0.f;
                    v1 = (c + 1 < len) ? expf(v1 * 0.125f) : 0.f;
                    __half2 hv = __floats2half2_rn(v0, v1);
                    rsum += __low2float(hv) + __high2float(hv);
                    if (CH) {
                        *(__half2*)(Ch + (size_t)z * sC + (size_t)r * ldc + c) = hv;
                        continue;
                    }
                }
                if (SCAT == 3) {
                    int b = z >> 3, hh = z & 7;
                    float* op = Cf + ((size_t)(b * SEQ + r)) * DIM + hh * HD + c;
                    *(float2*)op = make_float2(v0, v1);
                } else if (SCAT == 4) {
                    int b = r >> 9, n = r & 511, hh = c >> 6, dd = c & 63;
                    if (z == 1) {
                        float* op = Cf + ((size_t)(b * NH + hh) * HD + dd) * SEQ + n;
                        op[0] = v0;
                        op[SEQ] = v1;
                    } else {
                        float* op = Cf + (((size_t)(b * NH + hh)) * SEQ + n) * HD + dd;
                        *(float2*)op = make_float2(v0, v1);
                    }
                } else {
                    *(float2*)(Cf + (size_t)z * sC + (size_t)r * ldc + c) =
                        make_float2(v0, v1);
                }
            }
            if (EPI == 5) {
                rsum += __shfl_xor_sync(0xffffffffu, rsum, 1);
                rsum += __shfl_xor_sync(0xffffffffu, rsum, 2);
                if (tq == 0) atomicAdd(&rowsum[z * SEQ + r], rsum);
            }
        }
    }
}

// ---------------- outputs ----------------
__global__ void out1_kernel(float* __restrict__ out1) {
    int idx = blockIdx.x * blockDim.x + threadIdx.x;
    if (idx >= MR * DIM) return;
    int d = idx % DIM;
    int nb = idx / DIM;
    int b = nb % BATCH;
    int n = nb / BATCH;
    out1[idx] = g_h[((size_t)b * SEQ + n) * DIM + d];
}

__global__ void infw_kernel(const float* __restrict__ W) {
    int mrow = blockIdx.x;
    int t = threadIdx.x;  // 64
    float a[NCLS] = {0, 0, 0}, bv2[NCLS] = {0, 0, 0};
    const float* xp = g_h + (size_t)mrow * DIM;
    for (int d = t; d < DIM; d += 64) {
        float xv = xp[d];
#pragma unroll
        for (int c = 0; c < NCLS; c++) {
            a[c]   += xv * W[(size_t)d * NCLS + c];
            bv2[c] += xv * W[(size_t)(DIM + d) * NCLS + c];
        }
    }
    __shared__ float red[6][64];
#pragma unroll
    for (int c = 0; c < NCLS; c++) { red[c][t] = a[c]; red[3 + c][t] = bv2[c]; }
    __syncthreads();
    for (int sft = 32; sft >= 1; sft >>= 1) {
        if (t < sft) {
#pragma unroll
            for (int c = 0; c < 6; c++) red[c][t] += red[c][t + sft];
        }
        __syncthreads();
    }
    if (t == 0) {
#pragma unroll
        for (int c = 0; c < NCLS; c++) {
            g_la[mrow * NCLS + c] = red[c][0];
            g_lb[mrow * NCLS + c] = red[3 + c][0];
        }
    }
}

__global__ void pair_kernel(float* __restrict__ out2) {
    int idx = blockIdx.x * blockDim.x + threadIdx.x;
    if (idx >= SEQ * SEQ * BATCH) return;
    int b = idx % BATCH;
    int j = (idx / BATCH) % SEQ;
    int i = idx / (BATCH * SEQ);
    const float* lap = g_la + ((size_t)b * SEQ + i) * NCLS;
    const float* lbp = g_lb + ((size_t)b * SEQ + j) * NCLS;
    float v0 = lap[0] + lbp[0];
    float v1 = lap[1] + lbp[1];
    float v2 = lap[2] + lbp[2];
    float mx = fmaxf(v0, fmaxf(v1, v2));
    float lse = mx + logf(expf(v0 - mx) + expf(v1 - mx) + expf(v2 - mx));
    float* o = out2 + (size_t)idx * NCLS;
    o[0] = v0 - lse; o[1] = v1 - lse; o[2] = v2 - lse;
}

// ---------------- orchestration ----------------
extern "C" void kernel_launch(void* const* d_in, const int* in_sizes, int n_in,
                              void* d_out, int out_size) {
    (void)in_sizes; (void)n_in; (void)out_size;
    const int*   src     = (const int*)  d_in[0];
    const int*   lengths = (const int*)  d_in[1];
    const float* emb     = (const float*)d_in[2];
    const float* ln1_g   = (const float*)d_in[3];
    const float* ln1_b   = (const float*)d_in[4];
    const float* Wq      = (const float*)d_in[5];
    const float* bq      = (const float*)d_in[6];
    const float* Wk      = (const float*)d_in[7];
    const float* bk      = (const float*)d_in[8];
    const float* Wv      = (const float*)d_in[9];
    const float* bv      = (const float*)d_in[10];
    const float* Wo      = (const float*)d_in[11];
    const float* bo      = (const float*)d_in[12];
    const float* ln2_g   = (const float*)d_in[13];
    const float* ln2_b   = (const float*)d_in[14];
    const float* W1      = (const float*)d_in[15];
    const float* b1      = (const float*)d_in[16];
    const float* W2      = (const float*)d_in[17];
    const float* b2      = (const float*)d_in[18];
    const float* lnf_g   = (const float*)d_in[19];
    const float* lnf_b   = (const float*)d_in[20];
    const float* inf_W   = (const float*)d_in[21];
    float* out = (float*)d_out;

    float *px, *ph, *pq, *pk, *pv, *pctx, *pffn, *prs;
    __half* psc;
    cudaGetSymbolAddress((void**)&px,   g_x);
    cudaGetSymbolAddress((void**)&ph,   g_h);
    cudaGetSymbolAddress((void**)&pq,   g_q);
    cudaGetSymbolAddress((void**)&pk,   g_k);
    cudaGetSymbolAddress((void**)&pv,   g_v);
    cudaGetSymbolAddress((void**)&pctx, g_ctx);
    cudaGetSymbolAddress((void**)&pffn, g_ffn);
    cudaGetSymbolAddress((void**)&psc,  g_sc);
    cudaGetSymbolAddress((void**)&prs,  g_rs);

    embed_kernel<<<(MR * DIM + 255) / 256, 256>>>(src, emb);

    const long long sBH = (long long)SEQ * HD;
    const long long sSC = (long long)SEQ * SEQ;
    QKVArgs qe = {};

    for (int l = 0; l < NL; l++) {
        const float* wq = Wq + (size_t)l * DIM * DIM;
        const float* wk = Wk + (size_t)l * DIM * DIM;
        const float* wv = Wv + (size_t)l * DIM * DIM;
        const float* wo = Wo + (size_t)l * DIM * DIM;
        const float* w1 = W1 + (size_t)l * DIM * DFFN;
        const float* w2 = W2 + (size_t)l * DFFN * DIM;

        ln_kernel<<<MR, 128>>>(px, ph, ln1_g + l * DIM, ln1_b + l * DIM);

        // fused QKV projections: z = 0 (Q), 1 (K^T), 2 (V)
        QKVArgs qa;
        qa.w[0] = wq; qa.w[1] = wk; qa.w[2] = wv;
        qa.b[0] = bq + l * DIM; qa.b[1] = bk + l * DIM; qa.b[2] = bv + l * DIM;
        qa.o[0] = pq; qa.o[1] = pk; qa.o[2] = pv;
        dim3 gQKV(DIM / 128, MR / 128, 3);
        tgemm<128, 64, 0, 4, 0, 0><<<gQKV, 256>>>(ph, nullptr, nullptr, nullptr, nullptr,
                                                  DIM, DIM, DIM, DIM, 0, 0, 0,
                                                  nullptr, nullptr, qa);

        zero_rs_kernel<<<(NBH * SEQ + 255) / 256, 256>>>();

        // P_unnorm = exp(mask(QK^T/8)) -> fp16, rowsums accumulated
        dim3 gS(SEQ / 128, SEQ / 128, NBH);
        tgemm<128, 64, 5, 0, 0, 1><<<gS, 256>>>(pq, pk, nullptr, nullptr, psc,
                                                HD, HD, SEQ, SEQ, sBH, sBH, sSC,
                                                lengths, prs, qe);

        // ctx = (P_unnorm @ V) / rowsum, scatter into [B,N,D]
        dim3 gP(1, SEQ / 128, NBH);
        tgemm<64, 32, 4, 3, 1, 0><<<gP, 256>>>(psc, pv, nullptr, nullptr, pctx,
                                               SEQ, SEQ, HD, 0, sSC, sBH, 0,
                                               nullptr, prs, qe);

        dim3 gD(DIM / 128, MR / 128, 1);
        tgemm<128, 64, 1, 0, 0, 0><<<gD, 256>>>(pctx, wo, bo + l * DIM, px, px,
                                                DIM, DIM, DIM, DIM, 0, 0, 0,
                                                nullptr, nullptr, qe);

        ln_kernel<<<MR, 128>>>(px, ph, ln2_g + l * DIM, ln2_b + l * DIM);

        dim3 gF(DFFN / 128, MR / 128, 1);
        tgemm<128, 64, 2, 0, 0, 0><<<gF, 256>>>(ph, w1, b1 + l * DFFN, nullptr, pffn,
                                                DIM, DIM, DFFN, DFFN, 0, 0, 0,
                                                nullptr, nullptr, qe);
        tgemm<128, 64, 1, 0, 0, 0><<<gD, 256>>>(pffn, w2, b2 + l * DIM, px, px,
                                                DFFN, DFFN, DIM, DIM, 0, 0, 0,
                                                nullptr, nullptr, qe);
    }

    ln_kernel<<<MR, 128>>>(px, ph, lnf_g, lnf_b);

    out1_kernel<<<(MR * DIM + 255) / 256, 256>>>(out);
    infw_kernel<<<MR, 64>>>(inf_W);
    pair_kernel<<<(SEQ * SEQ * BATCH + 255) / 256, 256>>>(out + (size_t)MR * DIM);
}

// round 9
// speedup vs baseline: 3.4142x; 1.3429x over previous
#include <cuda_runtime.h>
#include <cuda_fp16.h>
#include <math.h>

constexpr int NL    = 4;
constexpr int DIM   = 512;
constexpr int NH    = 8;
constexpr int HD    = 64;
constexpr int DFFN  = 2048;
constexpr int SEQ   = 512;
constexpr int BATCH = 16;
constexpr int NCLS  = 3;
constexpr int MR    = BATCH * SEQ;  // 8192
constexpr int NBH   = BATCH * NH;   // 128

// ---------------- scratch ----------------
__device__ float  g_x  [MR * DIM];                 // residual stream (fp32)
__device__ float  g_hf [MR * DIM];                 // final LN output (fp32)
__device__ __half g_h  [MR * DIM];                 // LN output (fp16)
__device__ __half g_q  [MR * DIM];                 // [B,H,N,HD]
__device__ __half g_k  [MR * DIM];                 // [B,H,HD,N]
__device__ __half g_v  [MR * DIM];                 // [B,H,N,HD]
__device__ __half g_ctx[MR * DIM];
__device__ __half g_ffn[MR * DFFN];
__device__ __half g_sc [(size_t)NBH * SEQ * SEQ];  // exp(scores), fp16
__device__ __half g_wh [12582912];                 // all weights fp16
__device__ float  g_la [MR * NCLS];
__device__ float  g_lb [MR * NCLS];

// g_wh offsets (halves)
constexpr size_t OWQ = 0;
constexpr size_t OWK = OWQ + (size_t)NL * DIM * DIM;   // 1048576
constexpr size_t OWV = OWK + (size_t)NL * DIM * DIM;
constexpr size_t OWO = OWV + (size_t)NL * DIM * DIM;
constexpr size_t OW1 = OWO + (size_t)NL * DIM * DIM;   // 4194304
constexpr size_t OW2 = OW1 + (size_t)NL * DIM * DFFN;  // 8388608

struct QKVArgs {
    const __half* w[3];
    const float*  b[3];
    __half*       o[3];
};

// ---------------- fp32 -> fp16 weight conversion ----------------
__global__ void f2h4_kernel(const float* __restrict__ src, __half* __restrict__ dst, int n4) {
    int i = blockIdx.x * blockDim.x + threadIdx.x;
    if (i >= n4) return;
    float4 f = ((const float4*)src)[i];
    ((__half2*)dst)[2 * i]     = __floats2half2_rn(f.x, f.y);
    ((__half2*)dst)[2 * i + 1] = __floats2half2_rn(f.z, f.w);
}

// ---------------- embedding + PE ----------------
__global__ void embed_kernel(const int* __restrict__ src,
                             const float* __restrict__ emb) {
    int idx = blockIdx.x * blockDim.x + threadIdx.x;
    if (idx >= MR * DIM) return;
    int d = idx % DIM;
    int m = idx / DIM;
    int b = m / SEQ;
    int n = m % SEQ;
    int tok = src[n * BATCH + b];
    float e = emb[(size_t)tok * DIM + d] * 22.62741699796952f;
    int i2 = (d >> 1) * 2;
    float freq = expf((float)i2 * (-9.210340371976184f / (float)DIM));
    float ang = (float)n * freq;
    float pe = (d & 1) ? cosf(ang) : sinf(ang);
    g_x[idx] = e + pe;
}

// ---------------- LayerNorm (OH: 1 = half out, 0 = float out) -------------
template<int OH>
__global__ void ln_kernel(const float* __restrict__ in, void* __restrict__ out,
                          const float* __restrict__ gg, const float* __restrict__ bb) {
    int row = blockIdx.x;
    int t = threadIdx.x;
    const float* p = in + (size_t)row * DIM;
    float v[4];
    float s = 0.f, ss = 0.f;
#pragma unroll
    for (int i = 0; i < 4; i++) {
        float x = p[t + i * 128];
        v[i] = x; s += x; ss += x * x;
    }
#pragma unroll
    for (int off = 16; off >= 1; off >>= 1) {
        s  += __shfl_xor_sync(0xffffffffu, s, off);
        ss += __shfl_xor_sync(0xffffffffu, ss, off);
    }
    __shared__ float rs[4], rss[4];
    int w = t >> 5, lane = t & 31;
    if (lane == 0) { rs[w] = s; rss[w] = ss; }
    __syncthreads();
    float S  = rs[0] + rs[1] + rs[2] + rs[3];
    float SS = rss[0] + rss[1] + rss[2] + rss[3];
    float mean = S * (1.f / DIM);
    float var  = SS * (1.f / DIM) - mean * mean;
    float rstd = rsqrtf(var + 1e-6f);
#pragma unroll
    for (int i = 0; i < 4; i++) {
        int c = t + i * 128;
        float o = (v[i] - mean) * rstd * gg[c] + bb[c];
        if (OH) ((__half*)out)[(size_t)row * DIM + c] = __float2half(o);
        else    ((float*)out)[(size_t)row * DIM + c]  = o;
    }
}

// ---------------- fp16 mma helpers ----------------
__device__ __forceinline__ unsigned s2u(const void* p) {
    return (unsigned)__cvta_generic_to_shared(p);
}

__device__ __forceinline__ void mma_f16(float c[4], const unsigned a[4], const unsigned b[2]) {
    asm volatile(
        "mma.sync.aligned.m16n8k16.row.col.f32.f16.f16.f32 "
        "{%0,%1,%2,%3}, {%4,%5,%6,%7}, {%8,%9}, {%0,%1,%2,%3};"
        : "+f"(c[0]), "+f"(c[1]), "+f"(c[2]), "+f"(c[3])
        : "r"(a[0]), "r"(a[1]), "r"(a[2]), "r"(a[3]),
          "r"(b[0]), "r"(b[1]));
}

__device__ __forceinline__ float sum8h(uint4 v) {
    const __half2* h = (const __half2*)&v;
    float2 a = __half22float2(h[0]);
    float2 b = __half22float2(h[1]);
    float2 c = __half22float2(h[2]);
    float2 d = __half22float2(h[3]);
    return (a.x + a.y) + (b.x + b.y) + (c.x + c.y) + (d.x + d.y);
}

// ---------------- fp16 tensor-core GEMM (all-half inputs) -----------------
// C[z][M,N] = A[z][M,K] @ W[z][K,N]. BM=128, BK=32, 256 threads (8 warps).
// A smem [m][k] pitch 40 (ldmatrix.x4), B smem [k][n] pitch BN+8 (x2.trans).
// EPI: 0 bias, 1 bias+residual(f32), 2 bias+relu, 4 /rowsum(in-kernel), 5 exp+mask
// SCAT: 0 plain, 3 ctx scatter, 4 fused-QKV (z selects; z==1 -> K^T scatter)
// CH: output stored as half (1) or float (0)
template<int BN, int WM, int EPI, int SCAT, int CH>
__global__ __launch_bounds__(256, 2)
void tgemm(const __half* __restrict__ A, const __half* __restrict__ W,
           const float* __restrict__ bias, const float* __restrict__ resid,
           void* __restrict__ Cv, int K, int lda, int ldb, int ldc,
           long long sA, long long sB, long long sC,
           const int* __restrict__ lens, QKVArgs qa) {
    constexpr int BK  = 32;
    constexpr int LDA = 40;
    constexpr int LDB = BN + 8;
    constexpr int NWM = 128 / WM;
    constexpr int MT  = WM / 16;
    constexpr int BROWS = (BN == 128) ? 2 : 1;

    __shared__ __half As[2][128][LDA];
    __shared__ __half Bs[2][BK][LDB];
    __shared__ float  rs_sm[128];

    const int tid  = threadIdx.x;
    const int w    = tid >> 5;
    const int lane = tid & 31;
    const int g    = lane >> 2;
    const int tq   = lane & 3;
    const int lane15 = lane & 15;
    const int aoff = (lane >> 4) << 3;
    const int wrow = (w % NWM) * WM;
    const int wcol = (w / NWM) * 32;
    const int z    = blockIdx.z;
    const int row0 = blockIdx.y * 128;
    const int col0 = blockIdx.x * BN;

    const float* bias_p = bias;
    __half* Co_h = (__half*)Cv;
    float*  Co_f = (float*)Cv;
    if (SCAT == 4) {
        W      = qa.w[z];
        bias_p = qa.b[z];
        Co_h   = qa.o[z];
    } else {
        A += (size_t)z * sA;
        W += (size_t)z * sB;
    }

    const int arow = tid >> 1;
    const int acol = (tid & 1) * 16;
    const int brow = (BN == 128) ? (tid >> 4) : (tid >> 3);
    const int bcol = (BN == 128) ? (tid & 15) * 8 : (tid & 7) * 8;

    const __half* Ap = A + (size_t)(row0 + arow) * lda + acol;
    const __half* Wp = W + (size_t)brow * ldb + col0 + bcol;

    float C[MT][4][4];
#pragma unroll
    for (int i = 0; i < MT; i++)
#pragma unroll
        for (int j = 0; j < 4; j++)
#pragma unroll
            for (int q = 0; q < 4; q++) C[i][j][q] = 0.f;

    const int nblk = K / BK;
    float asum = 0.f;

    uint4 ahv, ahv2, bhv[BROWS];

    // prefetch block 0
    ahv  = *(const uint4*)(Ap);
    ahv2 = *(const uint4*)(Ap + 8);
    if (EPI == 4) asum += sum8h(ahv) + sum8h(ahv2);
#pragma unroll
    for (int rr = 0; rr < BROWS; rr++)
        bhv[rr] = *(const uint4*)(Wp + (size_t)rr * 16 * ldb);

    *(uint4*)&As[0][arow][acol]     = ahv;
    *(uint4*)&As[0][arow][acol + 8] = ahv2;
#pragma unroll
    for (int rr = 0; rr < BROWS; rr++)
        *(uint4*)&Bs[0][brow + rr * 16][bcol] = bhv[rr];
    __syncthreads();

    int s = 0;
    for (int blk = 0; blk < nblk; blk++) {
        if (blk + 1 < nblk) {
            const int k0 = (blk + 1) * BK;
            ahv  = *(const uint4*)(Ap + k0);
            ahv2 = *(const uint4*)(Ap + k0 + 8);
            if (EPI == 4) asum += sum8h(ahv) + sum8h(ahv2);
#pragma unroll
            for (int rr = 0; rr < BROWS; rr++)
                bhv[rr] = *(const uint4*)(Wp + (size_t)(k0 + rr * 16) * ldb);
        }

#pragma unroll
        for (int ks = 0; ks < 2; ks++) {
            const int kb = ks * 16;
            unsigned af[MT][4], bf[4][2];
#pragma unroll
            for (int mt = 0; mt < MT; mt++) {
                unsigned addr = s2u(&As[s][wrow + mt * 16 + lane15][kb + aoff]);
                asm volatile("ldmatrix.sync.aligned.m8n8.x4.shared.b16 {%0,%1,%2,%3}, [%4];"
                             : "=r"(af[mt][0]), "=r"(af[mt][1]), "=r"(af[mt][2]), "=r"(af[mt][3])
                             : "r"(addr));
            }
#pragma unroll
            for (int nt = 0; nt < 4; nt++) {
                unsigned addr = s2u(&Bs[s][kb + lane15][wcol + nt * 8]);
                asm volatile("ldmatrix.sync.aligned.m8n8.x2.trans.shared.b16 {%0,%1}, [%2];"
                             : "=r"(bf[nt][0]), "=r"(bf[nt][1])
                             : "r"(addr));
            }
#pragma unroll
            for (int mt = 0; mt < MT; mt++)
#pragma unroll
                for (int nt = 0; nt < 4; nt++)
                    mma_f16(C[mt][nt], af[mt], bf[nt]);
        }

        if (blk + 1 < nblk) {
            int ns = s ^ 1;
            *(uint4*)&As[ns][arow][acol]     = ahv;
            *(uint4*)&As[ns][arow][acol + 8] = ahv2;
#pragma unroll
            for (int rr = 0; rr < BROWS; rr++)
                *(uint4*)&Bs[ns][brow + rr * 16][bcol] = bhv[rr];
            __syncthreads();
            s = ns;
        }
    }

    // rowsum finalize (PV): pair covers full row
    if (EPI == 4) {
        float tot = asum + __shfl_xor_sync(0xffffffffu, asum, 1);
        if ((tid & 1) == 0) rs_sm[arow] = tot;
        __syncthreads();
    }

    // epilogue
    int len = 0;
    if (EPI == 5) len = lens[z >> 3];

#pragma unroll
    for (int mt = 0; mt < MT; mt++) {
#pragma unroll
        for (int half = 0; half < 2; half++) {
            int rl = wrow + mt * 16 + g + half * 8;
            int r  = row0 + rl;
            float inv = 1.f;
            if (EPI == 4) inv = 1.f / rs_sm[rl];
#pragma unroll
            for (int nt = 0; nt < 4; nt++) {
                int c = col0 + wcol + nt * 8 + tq * 2;
                float v0 = C[mt][nt][half * 2 + 0];
                float v1 = C[mt][nt][half * 2 + 1];
                if (EPI == 0 || EPI == 1 || EPI == 2) { v0 += bias_p[c]; v1 += bias_p[c + 1]; }
                if (EPI == 1) {
                    const float* rp = resid + (size_t)r * ldc + c;
                    v0 += rp[0]; v1 += rp[1];
                }
                if (EPI == 2) { v0 = fmaxf(v0, 0.f); v1 = fmaxf(v1, 0.f); }
                if (EPI == 4) { v0 *= inv; v1 *= inv; }
                if (EPI == 5) {
                    v0 = (c     < len) ? expf(v0 * 0.125f) : 0.f;
                    v1 = (c + 1 < len) ? expf(v1 * 0.125f) : 0.f;
                }
                if (SCAT == 3) {
                    int b = z >> 3, hh = z & 7;
                    *(__half2*)(Co_h + ((size_t)(b * SEQ + r)) * DIM + hh * HD + c) =
                        __floats2half2_rn(v0, v1);
                } else if (SCAT == 4) {
                    int b = r >> 9, n = r & 511, hh = c >> 6, dd = c & 63;
                    if (z == 1) {
                        __half* op = Co_h + ((size_t)(b * NH + hh) * HD + dd) * SEQ + n;
                        op[0]   = __float2half(v0);
                        op[SEQ] = __float2half(v1);
                    } else {
                        *(__half2*)(Co_h + (((size_t)(b * NH + hh)) * SEQ + n) * HD + dd) =
                            __floats2half2_rn(v0, v1);
                    }
                } else {
                    if (CH)
                        *(__half2*)(Co_h + (size_t)z * sC + (size_t)r * ldc + c) =
                            __floats2half2_rn(v0, v1);
                    else
                        *(float2*)(Co_f + (size_t)z * sC + (size_t)r * ldc + c) =
                            make_float2(v0, v1);
                }
            }
        }
    }
}

// ---------------- outputs ----------------
__global__ void out1_kernel(float* __restrict__ out1) {
    int idx = blockIdx.x * blockDim.x + threadIdx.x;
    if (idx >= MR * DIM) return;
    int d = idx % DIM;
    int nb = idx / DIM;
    int b = nb % BATCH;
    int n = nb / BATCH;
    out1[idx] = g_hf[((size_t)b * SEQ + n) * DIM + d];
}

__global__ void infw_kernel(const float* __restrict__ W) {
    int mrow = blockIdx.x;
    int t = threadIdx.x;  // 64
    float a[NCLS] = {0, 0, 0}, bv2[NCLS] = {0, 0, 0};
    const float* xp = g_hf + (size_t)mrow * DIM;
    for (int d = t; d < DIM; d += 64) {
        float xv = xp[d];
#pragma unroll
        for (int c = 0; c < NCLS; c++) {
            a[c]   += xv * W[(size_t)d * NCLS + c];
            bv2[c] += xv * W[(size_t)(DIM + d) * NCLS + c];
        }
    }
    __shared__ float red[6][64];
#pragma unroll
    for (int c = 0; c < NCLS; c++) { red[c][t] = a[c]; red[3 + c][t] = bv2[c]; }
    __syncthreads();
    for (int sft = 32; sft >= 1; sft >>= 1) {
        if (t < sft) {
#pragma unroll
            for (int c = 0; c < 6; c++) red[c][t] += red[c][t + sft];
        }
        __syncthreads();
    }
    if (t == 0) {
#pragma unroll
        for (int c = 0; c < NCLS; c++) {
            g_la[mrow * NCLS + c] = red[c][0];
            g_lb[mrow * NCLS + c] = red[3 + c][0];
        }
    }
}

__global__ void pair_kernel(float* __restrict__ out2) {
    int idx = blockIdx.x * blockDim.x + threadIdx.x;
    if (idx >= SEQ * SEQ * BATCH) return;
    int b = idx % BATCH;
    int j = (idx / BATCH) % SEQ;
    int i = idx / (BATCH * SEQ);
    const float* lap = g_la + ((size_t)b * SEQ + i) * NCLS;
    const float* lbp = g_lb + ((size_t)b * SEQ + j) * NCLS;
    float v0 = lap[0] + lbp[0];
    float v1 = lap[1] + lbp[1];
    float v2 = lap[2] + lbp[2];
    float mx = fmaxf(v0, fmaxf(v1, v2));
    float lse = mx + logf(expf(v0 - mx) + expf(v1 - mx) + expf(v2 - mx));
    float* o = out2 + (size_t)idx * NCLS;
    o[0] = v0 - lse; o[1] = v1 - lse; o[2] = v2 - lse;
}

// ---------------- orchestration ----------------
extern "C" void kernel_launch(void* const* d_in, const int* in_sizes, int n_in,
                              void* d_out, int out_size) {
    (void)in_sizes; (void)n_in; (void)out_size;
    const int*   src     = (const int*)  d_in[0];
    const int*   lengths = (const int*)  d_in[1];
    const float* emb     = (const float*)d_in[2];
    const float* ln1_g   = (const float*)d_in[3];
    const float* ln1_b   = (const float*)d_in[4];
    const float* Wq      = (const float*)d_in[5];
    const float* bq      = (const float*)d_in[6];
    const float* Wk      = (const float*)d_in[7];
    const float* bk      = (const float*)d_in[8];
    const float* Wv      = (const float*)d_in[9];
    const float* bv      = (const float*)d_in[10];
    const float* Wo      = (const float*)d_in[11];
    const float* bo      = (const float*)d_in[12];
    const float* ln2_g   = (const float*)d_in[13];
    const float* ln2_b   = (const float*)d_in[14];
    const float* W1      = (const float*)d_in[15];
    const float* b1      = (const float*)d_in[16];
    const float* W2      = (const float*)d_in[17];
    const float* b2      = (const float*)d_in[18];
    const float* lnf_g   = (const float*)d_in[19];
    const float* lnf_b   = (const float*)d_in[20];
    const float* inf_W   = (const float*)d_in[21];
    float* out = (float*)d_out;

    float *px, *phf;
    __half *ph, *pq, *pk, *pv, *pctx, *pffn, *psc, *pwh;
    cudaGetSymbolAddress((void**)&px,   g_x);
    cudaGetSymbolAddress((void**)&phf,  g_hf);
    cudaGetSymbolAddress((void**)&ph,   g_h);
    cudaGetSymbolAddress((void**)&pq,   g_q);
    cudaGetSymbolAddress((void**)&pk,   g_k);
    cudaGetSymbolAddress((void**)&pv,   g_v);
    cudaGetSymbolAddress((void**)&pctx, g_ctx);
    cudaGetSymbolAddress((void**)&pffn, g_ffn);
    cudaGetSymbolAddress((void**)&psc,  g_sc);
    cudaGetSymbolAddress((void**)&pwh,  g_wh);

    // one-time weight fp32->fp16 conversion
    const int nQ = NL * DIM * DIM;       // 1048576
    const int nF = NL * DIM * DFFN;      // 4194304
    f2h4_kernel<<<(nQ / 4 + 255) / 256, 256>>>(Wq, pwh + OWQ, nQ / 4);
    f2h4_kernel<<<(nQ / 4 + 255) / 256, 256>>>(Wk, pwh + OWK, nQ / 4);
    f2h4_kernel<<<(nQ / 4 + 255) / 256, 256>>>(Wv, pwh + OWV, nQ / 4);
    f2h4_kernel<<<(nQ / 4 + 255) / 256, 256>>>(Wo, pwh + OWO, nQ / 4);
    f2h4_kernel<<<(nF / 4 + 255) / 256, 256>>>(W1, pwh + OW1, nF / 4);
    f2h4_kernel<<<(nF / 4 + 255) / 256, 256>>>(W2, pwh + OW2, nF / 4);

    embed_kernel<<<(MR * DIM + 255) / 256, 256>>>(src, emb);

    const long long sBH = (long long)SEQ * HD;
    const long long sSC = (long long)SEQ * SEQ;
    QKVArgs qe = {};

    for (int l = 0; l < NL; l++) {
        const __half* wq = pwh + OWQ + (size_t)l * DIM * DIM;
        const __half* wk = pwh + OWK + (size_t)l * DIM * DIM;
        const __half* wv = pwh + OWV + (size_t)l * DIM * DIM;
        const __half* wo = pwh + OWO + (size_t)l * DIM * DIM;
        const __half* w1 = pwh + OW1 + (size_t)l * DIM * DFFN;
        const __half* w2 = pwh + OW2 + (size_t)l * DFFN * DIM;

        ln_kernel<1><<<MR, 128>>>(px, ph, ln1_g + l * DIM, ln1_b + l * DIM);

        QKVArgs qa;
        qa.w[0] = wq; qa.w[1] = wk; qa.w[2] = wv;
        qa.b[0] = bq + l * DIM; qa.b[1] = bk + l * DIM; qa.b[2] = bv + l * DIM;
        qa.o[0] = pq; qa.o[1] = pk; qa.o[2] = pv;
        dim3 gQKV(DIM / 128, MR / 128, 3);
        tgemm<128, 64, 0, 4, 1><<<gQKV, 256>>>(ph, nullptr, nullptr, nullptr, nullptr,
                                               DIM, DIM, DIM, DIM, 0, 0, 0,
                                               nullptr, qa);

        // P = exp(mask(QK^T/8)) -> fp16
        dim3 gS(SEQ / 128, SEQ / 128, NBH);
        tgemm<128, 64, 5, 0, 1><<<gS, 256>>>(pq, pk, nullptr, nullptr, psc,
                                             HD, HD, SEQ, SEQ, sBH, sBH, sSC,
                                             lengths, qe);

        // ctx = (P @ V) / rowsum (rowsum computed in-kernel from P loads)
        dim3 gP(1, SEQ / 128, NBH);
        tgemm<64, 32, 4, 3, 1><<<gP, 256>>>(psc, pv, nullptr, nullptr, pctx,
                                            SEQ, SEQ, HD, 0, sSC, sBH, 0,
                                            nullptr, qe);

        dim3 gD(DIM / 128, MR / 128, 1);
        tgemm<128, 64, 1, 0, 0><<<gD, 256>>>(pctx, wo, bo + l * DIM, px, px,
                                             DIM, DIM, DIM, DIM, 0, 0, 0,
                                             nullptr, qe);

        ln_kernel<1><<<MR, 128>>>(px, ph, ln2_g + l * DIM, ln2_b + l * DIM);

        dim3 gF(DFFN / 128, MR / 128, 1);
        tgemm<128, 64, 2, 0, 1><<<gF, 256>>>(ph, w1, b1 + l * DFFN, nullptr, pffn,
                                             DIM, DIM, DFFN, DFFN, 0, 0, 0,
                                             nullptr, qe);
        tgemm<128, 64, 1, 0, 0><<<gD, 256>>>(pffn, w2, b2 + l * DIM, px, px,
                                             DFFN, DFFN, DIM, DIM, 0, 0, 0,
                                             nullptr, qe);
    }

    ln_kernel<0><<<MR, 128>>>(px, phf, lnf_g, lnf_b);

    out1_kernel<<<(MR * DIM + 255) / 256, 256>>>(out);
    infw_kernel<<<MR, 64>>>(inf_W);
    pair_kernel<<<(SEQ * SEQ * BATCH + 255) / 256, 256>>>(out + (size_t)MR * DIM);
}

// round 10
// speedup vs baseline: 3.8015x; 1.1134x over previous
#include <cuda_runtime.h>
#include <cuda_fp16.h>
#include <math.h>

constexpr int NL    = 4;
constexpr int DIM   = 512;
constexpr int NH    = 8;
constexpr int HD    = 64;
constexpr int DFFN  = 2048;
constexpr int SEQ   = 512;
constexpr int BATCH = 16;
constexpr int NCLS  = 3;
constexpr int MR    = BATCH * SEQ;  // 8192
constexpr int NBH   = BATCH * NH;   // 128

// ---------------- scratch ----------------
__device__ float  g_x  [MR * DIM];                 // residual stream (fp32)
__device__ float  g_hf [MR * DIM];                 // final LN output (fp32)
__device__ __half g_h  [MR * DIM];                 // LN output (fp16)
__device__ __half g_q  [MR * DIM];                 // [B,H,N,HD] (pre-scaled by 1/8)
__device__ __half g_k  [MR * DIM];                 // [B,H,N,HD]
__device__ __half g_v  [MR * DIM];                 // [B,H,N,HD]
__device__ __half g_ctx[MR * DIM];
__device__ __half g_ffn[MR * DFFN];
__device__ __half g_wh [12582912];                 // all weights fp16
__device__ float  g_la [MR * NCLS];
__device__ float  g_lb [MR * NCLS];

constexpr size_t OWQ = 0;
constexpr size_t OWK = OWQ + (size_t)NL * DIM * DIM;
constexpr size_t OWV = OWK + (size_t)NL * DIM * DIM;
constexpr size_t OWO = OWV + (size_t)NL * DIM * DIM;
constexpr size_t OW1 = OWO + (size_t)NL * DIM * DIM;
constexpr size_t OW2 = OW1 + (size_t)NL * DIM * DFFN;

struct QKVArgs {
    const __half* w[3];
    const float*  b[3];
    __half*       o[3];
};

// ---------------- fp32 -> fp16 weight conversion ----------------
__global__ void f2h4_kernel(const float* __restrict__ src, __half* __restrict__ dst, int n4) {
    int i = blockIdx.x * blockDim.x + threadIdx.x;
    if (i >= n4) return;
    float4 f = ((const float4*)src)[i];
    ((__half2*)dst)[2 * i]     = __floats2half2_rn(f.x, f.y);
    ((__half2*)dst)[2 * i + 1] = __floats2half2_rn(f.z, f.w);
}

// ---------------- embedding + PE ----------------
__global__ void embed_kernel(const int* __restrict__ src,
                             const float* __restrict__ emb) {
    int idx = blockIdx.x * blockDim.x + threadIdx.x;
    if (idx >= MR * DIM) return;
    int d = idx % DIM;
    int m = idx / DIM;
    int b = m / SEQ;
    int n = m % SEQ;
    int tok = src[n * BATCH + b];
    float e = emb[(size_t)tok * DIM + d] * 22.62741699796952f;
    int i2 = (d >> 1) * 2;
    float freq = expf((float)i2 * (-9.210340371976184f / (float)DIM));
    float ang = (float)n * freq;
    float pe = (d & 1) ? cosf(ang) : sinf(ang);
    g_x[idx] = e + pe;
}

// ---------------- LayerNorm (OH: 1 = half out, 0 = float out) -------------
template<int OH>
__global__ void ln_kernel(const float* __restrict__ in, void* __restrict__ out,
                          const float* __restrict__ gg, const float* __restrict__ bb) {
    int row = blockIdx.x;
    int t = threadIdx.x;
    const float* p = in + (size_t)row * DIM;
    float v[4];
    float s = 0.f, ss = 0.f;
#pragma unroll
    for (int i = 0; i < 4; i++) {
        float x = p[t + i * 128];
        v[i] = x; s += x; ss += x * x;
    }
#pragma unroll
    for (int off = 16; off >= 1; off >>= 1) {
        s  += __shfl_xor_sync(0xffffffffu, s, off);
        ss += __shfl_xor_sync(0xffffffffu, ss, off);
    }
    __shared__ float rs[4], rss[4];
    int w = t >> 5, lane = t & 31;
    if (lane == 0) { rs[w] = s; rss[w] = ss; }
    __syncthreads();
    float S  = rs[0] + rs[1] + rs[2] + rs[3];
    float SS = rss[0] + rss[1] + rss[2] + rss[3];
    float mean = S * (1.f / DIM);
    float var  = SS * (1.f / DIM) - mean * mean;
    float rstd = rsqrtf(var + 1e-6f);
#pragma unroll
    for (int i = 0; i < 4; i++) {
        int c = t + i * 128;
        float o = (v[i] - mean) * rstd * gg[c] + bb[c];
        if (OH) ((__half*)out)[(size_t)row * DIM + c] = __float2half(o);
        else    ((float*)out)[(size_t)row * DIM + c]  = o;
    }
}

// ---------------- fp16 mma helpers ----------------
__device__ __forceinline__ unsigned s2u(const void* p) {
    return (unsigned)__cvta_generic_to_shared(p);
}

__device__ __forceinline__ void mma_f16(float c[4], const unsigned a[4], const unsigned b[2]) {
    asm volatile(
        "mma.sync.aligned.m16n8k16.row.col.f32.f16.f16.f32 "
        "{%0,%1,%2,%3}, {%4,%5,%6,%7}, {%8,%9}, {%0,%1,%2,%3};"
        : "+f"(c[0]), "+f"(c[1]), "+f"(c[2]), "+f"(c[3])
        : "r"(a[0]), "r"(a[1]), "r"(a[2]), "r"(a[3]),
          "r"(b[0]), "r"(b[1]));
}

// ---------------- fp16 tensor-core GEMM (all-half inputs) -----------------
// EPI: 0 bias, 1 bias+residual(f32), 2 bias+relu
// SCAT: 0 plain, 4 fused-QKV (z selects W/bias/out; z==0 scales by 1/8)
// CH: output stored as half (1) or float (0)
template<int BN, int WM, int EPI, int SCAT, int CH>
__global__ __launch_bounds__(256, 2)
void tgemm(const __half* __restrict__ A, const __half* __restrict__ W,
           const float* __restrict__ bias, const float* __restrict__ resid,
           void* __restrict__ Cv, int K, int lda, int ldb, int ldc,
           long long sA, long long sB, long long sC, QKVArgs qa) {
    constexpr int BK  = 32;
    constexpr int LDA = 40;
    constexpr int LDB = BN + 8;
    constexpr int NWM = 128 / WM;
    constexpr int MT  = WM / 16;
    constexpr int BROWS = (BN == 128) ? 2 : 1;

    __shared__ __half As[2][128][LDA];
    __shared__ __half Bs[2][BK][LDB];

    const int tid  = threadIdx.x;
    const int w    = tid >> 5;
    const int lane = tid & 31;
    const int g    = lane >> 2;
    const int tq   = lane & 3;
    const int lane15 = lane & 15;
    const int aoff = (lane >> 4) << 3;
    const int wrow = (w % NWM) * WM;
    const int wcol = (w / NWM) * 32;
    const int z    = blockIdx.z;
    const int row0 = blockIdx.y * 128;
    const int col0 = blockIdx.x * BN;

    const float* bias_p = bias;
    __half* Co_h = (__half*)Cv;
    float*  Co_f = (float*)Cv;
    if (SCAT == 4) {
        W      = qa.w[z];
        bias_p = qa.b[z];
        Co_h   = qa.o[z];
    } else {
        A += (size_t)z * sA;
        W += (size_t)z * sB;
    }

    const int arow = tid >> 1;
    const int acol = (tid & 1) * 16;
    const int brow = (BN == 128) ? (tid >> 4) : (tid >> 3);
    const int bcol = (BN == 128) ? (tid & 15) * 8 : (tid & 7) * 8;

    const __half* Ap = A + (size_t)(row0 + arow) * lda + acol;
    const __half* Wp = W + (size_t)brow * ldb + col0 + bcol;

    float C[MT][4][4];
#pragma unroll
    for (int i = 0; i < MT; i++)
#pragma unroll
        for (int j = 0; j < 4; j++)
#pragma unroll
            for (int q = 0; q < 4; q++) C[i][j][q] = 0.f;

    const int nblk = K / BK;

    uint4 ahv, ahv2, bhv[BROWS];

    ahv  = *(const uint4*)(Ap);
    ahv2 = *(const uint4*)(Ap + 8);
#pragma unroll
    for (int rr = 0; rr < BROWS; rr++)
        bhv[rr] = *(const uint4*)(Wp + (size_t)rr * 16 * ldb);

    *(uint4*)&As[0][arow][acol]     = ahv;
    *(uint4*)&As[0][arow][acol + 8] = ahv2;
#pragma unroll
    for (int rr = 0; rr < BROWS; rr++)
        *(uint4*)&Bs[0][brow + rr * 16][bcol] = bhv[rr];
    __syncthreads();

    int s = 0;
    for (int blk = 0; blk < nblk; blk++) {
        if (blk + 1 < nblk) {
            const int k0 = (blk + 1) * BK;
            ahv  = *(const uint4*)(Ap + k0);
            ahv2 = *(const uint4*)(Ap + k0 + 8);
#pragma unroll
            for (int rr = 0; rr < BROWS; rr++)
                bhv[rr] = *(const uint4*)(Wp + (size_t)(k0 + rr * 16) * ldb);
        }

#pragma unroll
        for (int ks = 0; ks < 2; ks++) {
            const int kb = ks * 16;
            unsigned af[MT][4], bf[4][2];
#pragma unroll
            for (int mt = 0; mt < MT; mt++) {
                unsigned addr = s2u(&As[s][wrow + mt * 16 + lane15][kb + aoff]);
                asm volatile("ldmatrix.sync.aligned.m8n8.x4.shared.b16 {%0,%1,%2,%3}, [%4];"
                             : "=r"(af[mt][0]), "=r"(af[mt][1]), "=r"(af[mt][2]), "=r"(af[mt][3])
                             : "r"(addr));
            }
#pragma unroll
            for (int nt = 0; nt < 4; nt++) {
                unsigned addr = s2u(&Bs[s][kb + lane15][wcol + nt * 8]);
                asm volatile("ldmatrix.sync.aligned.m8n8.x2.trans.shared.b16 {%0,%1}, [%2];"
                             : "=r"(bf[nt][0]), "=r"(bf[nt][1])
                             : "r"(addr));
            }
#pragma unroll
            for (int mt = 0; mt < MT; mt++)
#pragma unroll
                for (int nt = 0; nt < 4; nt++)
                    mma_f16(C[mt][nt], af[mt], bf[nt]);
        }

        if (blk + 1 < nblk) {
            int ns = s ^ 1;
            *(uint4*)&As[ns][arow][acol]     = ahv;
            *(uint4*)&As[ns][arow][acol + 8] = ahv2;
#pragma unroll
            for (int rr = 0; rr < BROWS; rr++)
                *(uint4*)&Bs[ns][brow + rr * 16][bcol] = bhv[rr];
            __syncthreads();
            s = ns;
        }
    }

#pragma unroll
    for (int mt = 0; mt < MT; mt++) {
#pragma unroll
        for (int half = 0; half < 2; half++) {
            int r = row0 + wrow + mt * 16 + g + half * 8;
#pragma unroll
            for (int nt = 0; nt < 4; nt++) {
                int c = col0 + wcol + nt * 8 + tq * 2;
                float v0 = C[mt][nt][half * 2 + 0] + bias_p[c];
                float v1 = C[mt][nt][half * 2 + 1] + bias_p[c + 1];
                if (EPI == 1) {
                    const float* rp = resid + (size_t)r * ldc + c;
                    v0 += rp[0]; v1 += rp[1];
                }
                if (EPI == 2) { v0 = fmaxf(v0, 0.f); v1 = fmaxf(v1, 0.f); }
                if (SCAT == 4) {
                    if (z == 0) { v0 *= 0.125f; v1 *= 0.125f; }  // fold 1/sqrt(HD) into Q
                    int b = r >> 9, n = r & 511, hh = c >> 6, dd = c & 63;
                    *(__half2*)(Co_h + (((size_t)(b * NH + hh)) * SEQ + n) * HD + dd) =
                        __floats2half2_rn(v0, v1);
                } else {
                    if (CH)
                        *(__half2*)(Co_h + (size_t)z * sC + (size_t)r * ldc + c) =
                            __floats2half2_rn(v0, v1);
                    else
                        *(float2*)(Co_f + (size_t)z * sC + (size_t)r * ldc + c) =
                            make_float2(v0, v1);
                }
            }
        }
    }
}

// ---------------- fused flash attention ----------------
// grid (SEQ/128, NBH), 256 threads (8 warps x 16 q-rows).
// Q pre-scaled by 1/8. K/V in [B,H,N,HD]. ctx written as half into [B,N,D].
constexpr int LDQ = 72;
constexpr int ATTN_SMEM = (128 * LDQ + 2 * 64 * LDQ + 2 * 64 * LDQ) * 2;  // 55296 B

__global__ __launch_bounds__(256, 1)
void attn_kernel(const int* __restrict__ lengths) {
    extern __shared__ __half sm[];
    __half (*Q_sm)[LDQ] = (__half(*)[LDQ])sm;                 // [128][72]
    __half (*K_sm)[LDQ] = (__half(*)[LDQ])(sm + 128 * LDQ);   // [2*64][72]
    __half (*V_sm)[LDQ] = (__half(*)[LDQ])(sm + 256 * LDQ);   // [2*64][72]

    const int tid  = threadIdx.x;
    const int w    = tid >> 5;
    const int lane = tid & 31;
    const int g    = lane >> 2;
    const int tq   = lane & 3;
    const int lane15 = lane & 15;
    const int aoff = (lane >> 4) << 3;
    const int bh = blockIdx.y;
    const int b  = bh >> 3;
    const int hh = bh & 7;
    const int q0 = blockIdx.x * 128;
    const int qbase = w * 16;
    const int len = lengths[b];

    const __half* Qg = g_q + ((size_t)bh * SEQ + q0) * HD;
    const __half* Kg = g_k + (size_t)bh * SEQ * HD;
    const __half* Vg = g_v + (size_t)bh * SEQ * HD;

    // load Q tile (128x64)
    {
        int r = tid >> 1, cb = (tid & 1) * 32;
        const __half* qp = Qg + (size_t)r * HD + cb;
#pragma unroll
        for (int i = 0; i < 4; i++)
            *(uint4*)&Q_sm[r][cb + i * 8] = *(const uint4*)(qp + i * 8);
    }
    // load K/V chunk 0 (64 keys)
    const int kr = tid >> 2, kc = (tid & 3) * 16;
    uint4 ka, kb2, va, vb;
    ka  = *(const uint4*)(Kg + (size_t)kr * HD + kc);
    kb2 = *(const uint4*)(Kg + (size_t)kr * HD + kc + 8);
    va  = *(const uint4*)(Vg + (size_t)kr * HD + kc);
    vb  = *(const uint4*)(Vg + (size_t)kr * HD + kc + 8);
    *(uint4*)&K_sm[kr][kc]     = ka;
    *(uint4*)&K_sm[kr][kc + 8] = kb2;
    *(uint4*)&V_sm[kr][kc]     = va;
    *(uint4*)&V_sm[kr][kc + 8] = vb;
    __syncthreads();

    // preload Q fragments (m16 x k64)
    unsigned qf[4][4];
#pragma unroll
    for (int k = 0; k < 4; k++) {
        unsigned addr = s2u(&Q_sm[qbase + lane15][k * 16 + aoff]);
        asm volatile("ldmatrix.sync.aligned.m8n8.x4.shared.b16 {%0,%1,%2,%3}, [%4];"
                     : "=r"(qf[k][0]), "=r"(qf[k][1]), "=r"(qf[k][2]), "=r"(qf[k][3])
                     : "r"(addr));
    }

    float ctx[8][4];
#pragma unroll
    for (int i = 0; i < 8; i++)
#pragma unroll
        for (int j = 0; j < 4; j++) ctx[i][j] = 0.f;
    float rs0 = 0.f, rs1 = 0.f;

    int s = 0;
    for (int c = 0; c < 8; c++) {
        if (c + 1 < 8) {
            const __half* kp = Kg + (size_t)((c + 1) * 64 + kr) * HD + kc;
            const __half* vp = Vg + (size_t)((c + 1) * 64 + kr) * HD + kc;
            ka  = *(const uint4*)(kp);
            kb2 = *(const uint4*)(kp + 8);
            va  = *(const uint4*)(vp);
            vb  = *(const uint4*)(vp + 8);
        }

        // S = Q @ K^T for 64 keys
        float S[8][4];
#pragma unroll
        for (int i = 0; i < 8; i++)
#pragma unroll
            for (int j = 0; j < 4; j++) S[i][j] = 0.f;
#pragma unroll
        for (int k = 0; k < 4; k++) {
            unsigned bk[4][4];
#pragma unroll
            for (int p = 0; p < 4; p++) {
                unsigned addr = s2u(&K_sm[s * 64 + p * 16 + lane15][k * 16 + aoff]);
                asm volatile("ldmatrix.sync.aligned.m8n8.x4.shared.b16 {%0,%1,%2,%3}, [%4];"
                             : "=r"(bk[p][0]), "=r"(bk[p][1]), "=r"(bk[p][2]), "=r"(bk[p][3])
                             : "r"(addr));
            }
#pragma unroll
            for (int p = 0; p < 4; p++) {
                unsigned bfa[2] = {bk[p][0], bk[p][2]};
                unsigned bfb[2] = {bk[p][1], bk[p][3]};
                mma_f16(S[2 * p],     qf[k], bfa);
                mma_f16(S[2 * p + 1], qf[k], bfb);
            }
        }

        // exp + mask -> P halves (rows g / g+8), accumulate rowsums from halves
        unsigned pl[8], ph[8];
        const int kbase = c * 64 + tq * 2;
#pragma unroll
        for (int nt = 0; nt < 8; nt++) {
            int key = kbase + nt * 8;
            bool m0 = key < len, m1 = key + 1 < len;
            float e0 = m0 ? __expf(S[nt][0]) : 0.f;
            float e1 = m1 ? __expf(S[nt][1]) : 0.f;
            float e2 = m0 ? __expf(S[nt][2]) : 0.f;
            float e3 = m1 ? __expf(S[nt][3]) : 0.f;
            __half2 h0 = __floats2half2_rn(e0, e1);
            __half2 h1 = __floats2half2_rn(e2, e3);
            pl[nt] = *(unsigned*)&h0;
            ph[nt] = *(unsigned*)&h1;
            float2 f0 = __half22float2(h0);
            float2 f1 = __half22float2(h1);
            rs0 += f0.x + f0.y;
            rs1 += f1.x + f1.y;
        }

        // ctx += P @ V
#pragma unroll
        for (int j = 0; j < 4; j++) {
            unsigned af[4] = {pl[2 * j], ph[2 * j], pl[2 * j + 1], ph[2 * j + 1]};
#pragma unroll
            for (int nt = 0; nt < 8; nt++) {
                unsigned bf[2];
                unsigned addr = s2u(&V_sm[s * 64 + j * 16 + lane15][nt * 8]);
                asm volatile("ldmatrix.sync.aligned.m8n8.x2.trans.shared.b16 {%0,%1}, [%2];"
                             : "=r"(bf[0]), "=r"(bf[1])
                             : "r"(addr));
                mma_f16(ctx[nt], af, bf);
            }
        }

        if (c + 1 < 8) {
            int ns = s ^ 1;
            *(uint4*)&K_sm[ns * 64 + kr][kc]     = ka;
            *(uint4*)&K_sm[ns * 64 + kr][kc + 8] = kb2;
            *(uint4*)&V_sm[ns * 64 + kr][kc]     = va;
            *(uint4*)&V_sm[ns * 64 + kr][kc + 8] = vb;
            __syncthreads();
            s = ns;
        }
    }

    // finalize rowsums (quad reduce) and write ctx
    rs0 += __shfl_xor_sync(0xffffffffu, rs0, 1);
    rs0 += __shfl_xor_sync(0xffffffffu, rs0, 2);
    rs1 += __shfl_xor_sync(0xffffffffu, rs1, 1);
    rs1 += __shfl_xor_sync(0xffffffffu, rs1, 2);
    float i0 = 1.f / rs0;
    float i1 = 1.f / rs1;

    int q = q0 + qbase + g;
#pragma unroll
    for (int nt = 0; nt < 8; nt++) {
        int col = hh * HD + nt * 8 + tq * 2;
        *(__half2*)(g_ctx + (size_t)(b * SEQ + q) * DIM + col) =
            __floats2half2_rn(ctx[nt][0] * i0, ctx[nt][1] * i0);
        *(__half2*)(g_ctx + (size_t)(b * SEQ + q + 8) * DIM + col) =
            __floats2half2_rn(ctx[nt][2] * i1, ctx[nt][3] * i1);
    }
}

// ---------------- outputs ----------------
__global__ void out1_kernel(float* __restrict__ out1) {
    int idx = blockIdx.x * blockDim.x + threadIdx.x;
    if (idx >= MR * DIM) return;
    int d = idx % DIM;
    int nb = idx / DIM;
    int b = nb % BATCH;
    int n = nb / BATCH;
    out1[idx] = g_hf[((size_t)b * SEQ + n) * DIM + d];
}

__global__ void infw_kernel(const float* __restrict__ W) {
    int mrow = blockIdx.x;
    int t = threadIdx.x;  // 64
    float a[NCLS] = {0, 0, 0}, bv2[NCLS] = {0, 0, 0};
    const float* xp = g_hf + (size_t)mrow * DIM;
    for (int d = t; d < DIM; d += 64) {
        float xv = xp[d];
#pragma unroll
        for (int c = 0; c < NCLS; c++) {
            a[c]   += xv * W[(size_t)d * NCLS + c];
            bv2[c] += xv * W[(size_t)(DIM + d) * NCLS + c];
        }
    }
    __shared__ float red[6][64];
#pragma unroll
    for (int c = 0; c < NCLS; c++) { red[c][t] = a[c]; red[3 + c][t] = bv2[c]; }
    __syncthreads();
    for (int sft = 32; sft >= 1; sft >>= 1) {
        if (t < sft) {
#pragma unroll
            for (int c = 0; c < 6; c++) red[c][t] += red[c][t + sft];
        }
        __syncthreads();
    }
    if (t == 0) {
#pragma unroll
        for (int c = 0; c < NCLS; c++) {
            g_la[mrow * NCLS + c] = red[c][0];
            g_lb[mrow * NCLS + c] = red[3 + c][0];
        }
    }
}

__global__ void pair_kernel(float* __restrict__ out2) {
    int idx = blockIdx.x * blockDim.x + threadIdx.x;
    if (idx >= SEQ * SEQ * BATCH) return;
    int b = idx % BATCH;
    int j = (idx / BATCH) % SEQ;
    int i = idx / (BATCH * SEQ);
    const float* lap = g_la + ((size_t)b * SEQ + i) * NCLS;
    const float* lbp = g_lb + ((size_t)b * SEQ + j) * NCLS;
    float v0 = lap[0] + lbp[0];
    float v1 = lap[1] + lbp[1];
    float v2 = lap[2] + lbp[2];
    float mx = fmaxf(v0, fmaxf(v1, v2));
    float lse = mx + logf(expf(v0 - mx) + expf(v1 - mx) + expf(v2 - mx));
    float* o = out2 + (size_t)idx * NCLS;
    o[0] = v0 - lse; o[1] = v1 - lse; o[2] = v2 - lse;
}

// ---------------- orchestration ----------------
extern "C" void kernel_launch(void* const* d_in, const int* in_sizes, int n_in,
                              void* d_out, int out_size) {
    (void)in_sizes; (void)n_in; (void)out_size;
    const int*   src     = (const int*)  d_in[0];
    const int*   lengths = (const int*)  d_in[1];
    const float* emb     = (const float*)d_in[2];
    const float* ln1_g   = (const float*)d_in[3];
    const float* ln1_b   = (const float*)d_in[4];
    const float* Wq      = (const float*)d_in[5];
    const float* bq      = (const float*)d_in[6];
    const float* Wk      = (const float*)d_in[7];
    const float* bk      = (const float*)d_in[8];
    const float* Wv      = (const float*)d_in[9];
    const float* bv      = (const float*)d_in[10];
    const float* Wo      = (const float*)d_in[11];
    const float* bo      = (const float*)d_in[12];
    const float* ln2_g   = (const float*)d_in[13];
    const float* ln2_b   = (const float*)d_in[14];
    const float* W1      = (const float*)d_in[15];
    const float* b1      = (const float*)d_in[16];
    const float* W2      = (const float*)d_in[17];
    const float* b2      = (const float*)d_in[18];
    const float* lnf_g   = (const float*)d_in[19];
    const float* lnf_b   = (const float*)d_in[20];
    const float* inf_W   = (const float*)d_in[21];
    float* out = (float*)d_out;

    float *px, *phf;
    __half *ph, *pq, *pk, *pv, *pctx, *pffn, *pwh;
    cudaGetSymbolAddress((void**)&px,   g_x);
    cudaGetSymbolAddress((void**)&phf,  g_hf);
    cudaGetSymbolAddress((void**)&ph,   g_h);
    cudaGetSymbolAddress((void**)&pq,   g_q);
    cudaGetSymbolAddress((void**)&pk,   g_k);
    cudaGetSymbolAddress((void**)&pv,   g_v);
    cudaGetSymbolAddress((void**)&pctx, g_ctx);
    cudaGetSymbolAddress((void**)&pffn, g_ffn);
    cudaGetSymbolAddress((void**)&pwh,  g_wh);

    cudaFuncSetAttribute(attn_kernel, cudaFuncAttributeMaxDynamicSharedMemorySize,
                         ATTN_SMEM);

    // one-time weight fp32->fp16 conversion
    const int nQ = NL * DIM * DIM;
    const int nF = NL * DIM * DFFN;
    f2h4_kernel<<<(nQ / 4 + 255) / 256, 256>>>(Wq, pwh + OWQ, nQ / 4);
    f2h4_kernel<<<(nQ / 4 + 255) / 256, 256>>>(Wk, pwh + OWK, nQ / 4);
    f2h4_kernel<<<(nQ / 4 + 255) / 256, 256>>>(Wv, pwh + OWV, nQ / 4);
    f2h4_kernel<<<(nQ / 4 + 255) / 256, 256>>>(Wo, pwh + OWO, nQ / 4);
    f2h4_kernel<<<(nF / 4 + 255) / 256, 256>>>(W1, pwh + OW1, nF / 4);
    f2h4_kernel<<<(nF / 4 + 255) / 256, 256>>>(W2, pwh + OW2, nF / 4);

    embed_kernel<<<(MR * DIM + 255) / 256, 256>>>(src, emb);

    QKVArgs qe = {};

    for (int l = 0; l < NL; l++) {
        const __half* wq = pwh + OWQ + (size_t)l * DIM * DIM;
        const __half* wk = pwh + OWK + (size_t)l * DIM * DIM;
        const __half* wv = pwh + OWV + (size_t)l * DIM * DIM;
        const __half* wo = pwh + OWO + (size_t)l * DIM * DIM;
        const __half* w1 = pwh + OW1 + (size_t)l * DIM * DFFN;
        const __half* w2 = pwh + OW2 + (size_t)l * DFFN * DIM;

        ln_kernel<1><<<MR, 128>>>(px, ph, ln1_g + l * DIM, ln1_b + l * DIM);

        QKVArgs qa;
        qa.w[0] = wq; qa.w[1] = wk; qa.w[2] = wv;
        qa.b[0] = bq + l * DIM; qa.b[1] = bk + l * DIM; qa.b[2] = bv + l * DIM;
        qa.o[0] = pq; qa.o[1] = pk; qa.o[2] = pv;
        dim3 gQKV(DIM / 128, MR / 128, 3);
        tgemm<128, 64, 0, 4, 1><<<gQKV, 256>>>(ph, nullptr, nullptr, nullptr, nullptr,
                                               DIM, DIM, DIM, DIM, 0, 0, 0, qa);

        // fused flash attention: ctx = softmax(QK^T) @ V  (no P materialization)
        dim3 gA(SEQ / 128, NBH);
        attn_kernel<<<gA, 256, ATTN_SMEM>>>(lengths);

        dim3 gD(DIM / 128, MR / 128, 1);
        tgemm<128, 64, 1, 0, 0><<<gD, 256>>>(pctx, wo, bo + l * DIM, px, px,
                                             DIM, DIM, DIM, DIM, 0, 0, 0, qe);

        ln_kernel<1><<<MR, 128>>>(px, ph, ln2_g + l * DIM, ln2_b + l * DIM);

        dim3 gF(DFFN / 128, MR / 128, 1);
        tgemm<128, 64, 2, 0, 1><<<gF, 256>>>(ph, w1, b1 + l * DFFN, nullptr, pffn,
                                             DIM, DIM, DFFN, DFFN, 0, 0, 0, qe);
        tgemm<128, 64, 1, 0, 0><<<gD, 256>>>(pffn, w2, b2 + l * DIM, px, px,
                                             DFFN, DFFN, DIM, DIM, 0, 0, 0, qe);
    }

    ln_kernel<0><<<MR, 128>>>(px, phf, lnf_g, lnf_b);

    out1_kernel<<<(MR * DIM + 255) / 256, 256>>>(out);
    infw_kernel<<<MR, 64>>>(inf_W);
    pair_kernel<<<(SEQ * SEQ * BATCH + 255) / 256, 256>>>(out + (size_t)MR * DIM);
}